// round 1
// baseline (speedup 1.0000x reference)
#include <cuda_runtime.h>
#include <cstdint>
#include <math.h>

// ModSTDP: bit-exact replay of JAX threefry2x32 (partitionable scheme) STDP update.
// weight shape (R,C,COUT,CIN,KH,KW) = (16,16,64,16,8,8) -> 16,777,216 f32 elements.
// STRIDE=0 => bx depends only on (ci,kh,kw) [1024 vals]; by on (o,r,c) [16384 vals].

#define N_ELEMS   16777216
#define XTAB_N    1024     // CIN*KH*KW
#define YTAB_N    16384    // COUT*R*C

__device__ uint8_t g_xtab[XTAB_N];
__device__ uint8_t g_ytab[YTAB_N];

struct Params {
    uint32_t k0[5], k1[5];                       // split(key(42),5) subkeys
    uint32_t Tsearch, Tcapture, Tbackoff, Tminus, Tumin;
    uint32_t TFM[8], TFP[8];                     // F_minus / F_plus integer thresholds per weight value
};

__host__ __device__ __forceinline__ uint32_t rotl32(uint32_t x, int r) {
    return (x << r) | (x >> (32 - r));
}

// Threefry-2x32, 20 rounds (Random123 / JAX threefry2x32_p)
__host__ __device__ __forceinline__ void tf2x32(uint32_t k0, uint32_t k1,
                                                uint32_t x0, uint32_t x1,
                                                uint32_t& o0, uint32_t& o1) {
    uint32_t ks2 = k0 ^ k1 ^ 0x1BD11BDAu;
    x0 += k0; x1 += k1;
#define TFR(r) { x0 += x1; x1 = rotl32(x1, r); x1 ^= x0; }
    TFR(13) TFR(15) TFR(26) TFR(6)   x0 += k1;  x1 += ks2 + 1u;
    TFR(17) TFR(29) TFR(16) TFR(24)  x0 += ks2; x1 += k0  + 2u;
    TFR(13) TFR(15) TFR(26) TFR(6)   x0 += k0;  x1 += k1  + 3u;
    TFR(17) TFR(29) TFR(16) TFR(24)  x0 += k1;  x1 += ks2 + 4u;
    TFR(13) TFR(15) TFR(26) TFR(6)   x0 += ks2; x1 += k0  + 5u;
#undef TFR
    o0 = x0; o1 = x1;
}

// Build bx/by lookup tables: x_times = 7 - sum_t input_spikes, y_times = 7 - sum_t output_spikes
__global__ void __launch_bounds__(256) prep_kernel(const int* __restrict__ inS,
                                                   const int* __restrict__ outS) {
    int t = blockIdx.x * 256 + threadIdx.x;
    if (t < YTAB_N) {
        int s = 0;
#pragma unroll
        for (int tt = 0; tt < 7; ++tt) s += outS[tt * YTAB_N + t];
        g_ytab[t] = (uint8_t)(7 - s);
    } else if (t < YTAB_N + XTAB_N) {
        int u = t - YTAB_N;
        int s = 0;
#pragma unroll
        for (int tt = 0; tt < 7; ++tt) s += inS[tt * XTAB_N + u];
        g_xtab[u] = (uint8_t)(7 - s);
    }
}

__global__ void __launch_bounds__(256) stdp_main(const float* __restrict__ w,
                                                 float* __restrict__ out,
                                                 Params P) {
    __shared__ uint32_t sTFM[8], sTFP[8];
    if (threadIdx.x < 8)       sTFM[threadIdx.x] = P.TFM[threadIdx.x];
    else if (threadIdx.x < 16) sTFP[threadIdx.x - 8] = P.TFP[threadIdx.x - 8];
    __syncthreads();

    uint32_t i = (blockIdx.x * 256u + threadIdx.x) * 4u;
    if (i >= (uint32_t)N_ELEMS) return;

    // flattened weight index: ((((r*16 + c)*64 + o)*16 + ci)*8 + kh)*8 + kw
    uint32_t khkw = i & 63u;
    uint32_t ci   = (i >> 6)  & 15u;
    uint32_t o    = (i >> 10) & 63u;
    uint32_t c    = (i >> 16) & 15u;
    uint32_t r    = (i >> 20) & 15u;

    uint32_t xword = *reinterpret_cast<const uint32_t*>(&g_xtab[ci * 64u + khkw]); // 4 bx bytes
    uint32_t by    = g_ytab[o * 256u + r * 16u + c];
    bool Bflag = (by == 7u);

    float4 wv = *reinterpret_cast<const float4*>(w + i);
    float wf[4] = {wv.x, wv.y, wv.z, wv.w};
    float res[4];

#pragma unroll
    for (int e = 0; e < 4; ++e) {
        uint32_t idx = i + (uint32_t)e;
        uint32_t bx = (xword >> (8 * e)) & 0xFFu;

        // exclusive prob selection (probs as integer thresholds on m = bits>>9)
        uint32_t Tp = 0u, Tm = 0u;
        if (bx != 7u) {
            if (Bflag)          Tp = P.Tsearch;
            else if (bx <= by)  Tp = P.Tcapture;
            else                Tm = P.Tminus;
        } else if (!Bflag) {
            Tm = P.Tbackoff;
        }

        // 5 uniform draws: partitionable scheme -> bits = o0 ^ o1 of threefry(k_j, (0, idx))
        uint32_t m[5];
#pragma unroll
        for (int kk = 0; kk < 5; ++kk) {
            uint32_t a, b;
            tf2x32(P.k0[kk], P.k1[kk], 0u, idx, a, b);
            m[kk] = (a ^ b) >> 9;
        }

        int wi = (int)wf[e];                     // weights are exact integers 0..7
        bool umin = m[4] < P.Tumin;
        bool fp = (m[3] < sTFP[wi]) || umin;     // F_plus
        bool fm = (m[2] < sTFM[wi]) || umin;     // F_minus
        int d = (int)((m[0] < Tp) && fp) - (int)((m[1] < Tm) && fm);
        int nw = wi + d;
        nw = min(max(nw, 0), 7);
        res[e] = (float)nw;
    }

    *reinterpret_cast<float4*>(out + i) = make_float4(res[0], res[1], res[2], res[3]);
}

static inline uint32_t thresh_from_prob(float p) {
    if (p <= 0.0f) return 0u;
    double v = ceil((double)p * 8388608.0);     // 2^23; u = m*2^-23 exactly, u<p <=> m<ceil(p*2^23)
    if (v < 0.0) return 0u;
    if (v > 4294967295.0) return 0xFFFFFFFFu;
    return (uint32_t)v;
}

extern "C" void kernel_launch(void* const* d_in, const int* in_sizes, int n_in,
                              void* d_out, int out_size) {
    const float* w    = (const float*)d_in[0];
    const int*   inS  = (const int*)d_in[1];
    const int*   outS = (const int*)d_in[2];

    Params P;
    // jax.random.key(42) -> data (0, 42); split(key, 5) fold-like: subkey_j = threefry((0,42),(0,j))
    for (int j = 0; j < 5; ++j)
        tf2x32(0u, 42u, 0u, (uint32_t)j, P.k0[j], P.k1[j]);

    P.Tcapture = thresh_from_prob((float)0.102);
    P.Tminus   = thresh_from_prob((float)0.051);
    P.Tsearch  = thresh_from_prob((float)0.032);
    P.Tbackoff = thresh_from_prob((float)0.96);
    P.Tumin    = thresh_from_prob((float)0.008);

    const float inv7 = (float)(1.0 / 7.0);      // matches jnp f32(1.0/MAXW)
    for (int ww = 0; ww < 8; ++ww) {
        float rr = (float)ww * inv7;
        float a  = (1.0f - rr) * (1.0f + rr);   // F_minus prob
        float b  = rr * (2.0f - rr);            // F_plus prob
        P.TFM[ww] = thresh_from_prob(a);
        P.TFP[ww] = thresh_from_prob(b);
    }

    prep_kernel<<<(YTAB_N + XTAB_N + 255) / 256, 256>>>(inS, outS);
    stdp_main<<<N_ELEMS / 1024, 256>>>(w, (float*)d_out, P);
}

// round 2
// speedup vs baseline: 1.3984x; 1.3984x over previous
#include <cuda_runtime.h>
#include <cstdint>
#include <math.h>

// ModSTDP: bit-exact replay of JAX threefry2x32 (partitionable scheme) STDP update.
// weight shape (R,C,COUT,CIN,KH,KW) = (16,16,64,16,8,8) -> 16,777,216 f32 elements.
// STRIDE=0 => bx depends only on (ci,kh,kw) [1024 vals]; by on (o,r,c) [16384 vals].
//
// R2: branch exclusivity => each element is either a "plus" or "minus" element,
// so only 3 of the 5 uniform draws can affect it. Select the key pair per
// element (branchless SEL) and do 3 threefry calls instead of 5.
// Also compare raw (o0^o1) against pre-shifted thresholds (T<<9) to drop SHFs.

#define N_ELEMS   16777216
#define XTAB_N    1024     // CIN*KH*KW
#define YTAB_N    16384    // COUT*R*C

__device__ uint8_t g_xtab[XTAB_N];
__device__ uint8_t g_ytab[YTAB_N];

struct Params {
    uint32_t k0[5], k1[5];                        // split(key(42),5) subkeys
    uint32_t Tsearch9, Tcap9, Tback9, Tminus9, Tumin9;  // thresholds << 9 (clamped)
    uint32_t TF9[16];                             // [0..7]=F_minus<<9, [8..15]=F_plus<<9 per weight value
};

__host__ __device__ __forceinline__ uint32_t rotl32(uint32_t x, int r) {
    return (x << r) | (x >> (32 - r));
}

// Threefry-2x32, 20 rounds (Random123 / JAX threefry2x32_p)
__host__ __device__ __forceinline__ void tf2x32(uint32_t k0, uint32_t k1,
                                                uint32_t x0, uint32_t x1,
                                                uint32_t& o0, uint32_t& o1) {
    uint32_t ks2 = k0 ^ k1 ^ 0x1BD11BDAu;
    x0 += k0; x1 += k1;
#define TFR(r) { x0 += x1; x1 = rotl32(x1, r); x1 ^= x0; }
    TFR(13) TFR(15) TFR(26) TFR(6)   x0 += k1;  x1 += ks2 + 1u;
    TFR(17) TFR(29) TFR(16) TFR(24)  x0 += ks2; x1 += k0  + 2u;
    TFR(13) TFR(15) TFR(26) TFR(6)   x0 += k0;  x1 += k1  + 3u;
    TFR(17) TFR(29) TFR(16) TFR(24)  x0 += k1;  x1 += ks2 + 4u;
    TFR(13) TFR(15) TFR(26) TFR(6)   x0 += ks2; x1 += k0  + 5u;
#undef TFR
    o0 = x0; o1 = x1;
}

// Build bx/by lookup tables: x_times = 7 - sum_t input_spikes, y_times = 7 - sum_t output_spikes
__global__ void __launch_bounds__(256) prep_kernel(const int* __restrict__ inS,
                                                   const int* __restrict__ outS) {
    int t = blockIdx.x * 256 + threadIdx.x;
    if (t < YTAB_N) {
        int s = 0;
#pragma unroll
        for (int tt = 0; tt < 7; ++tt) s += outS[tt * YTAB_N + t];
        g_ytab[t] = (uint8_t)(7 - s);
    } else if (t < YTAB_N + XTAB_N) {
        int u = t - YTAB_N;
        int s = 0;
#pragma unroll
        for (int tt = 0; tt < 7; ++tt) s += inS[tt * XTAB_N + u];
        g_xtab[u] = (uint8_t)(7 - s);
    }
}

__global__ void __launch_bounds__(256) stdp_main(const float* __restrict__ w,
                                                 float* __restrict__ out,
                                                 Params P) {
    __shared__ uint32_t sTF9[16];
    if (threadIdx.x < 16) sTF9[threadIdx.x] = P.TF9[threadIdx.x];
    __syncthreads();

    uint32_t i = (blockIdx.x * 256u + threadIdx.x) * 4u;
    if (i >= (uint32_t)N_ELEMS) return;

    // flattened weight index: ((((r*16 + c)*64 + o)*16 + ci)*8 + kh)*8 + kw
    uint32_t khkw = i & 63u;
    uint32_t ci   = (i >> 6)  & 15u;
    uint32_t o    = (i >> 10) & 63u;
    uint32_t c    = (i >> 16) & 15u;
    uint32_t r    = (i >> 20) & 15u;

    uint32_t xword = *reinterpret_cast<const uint32_t*>(&g_xtab[ci * 64u + khkw]); // 4 bx bytes
    uint32_t by    = g_ytab[o * 256u + r * 16u + c];
    bool Bflag = (by == 7u);

    float4 wv = *reinterpret_cast<const float4*>(w + i);
    float wf[4] = {wv.x, wv.y, wv.z, wv.w};
    float res[4];

#pragma unroll
    for (int e = 0; e < 4; ++e) {
        uint32_t idx = i + (uint32_t)e;
        uint32_t bx = (xword >> (8 * e)) & 0xFFu;

        bool A = (bx == 7u);
        // exclusive branch: plus-elements use (k0 gate, k3 F_plus); minus use (k1, k2)
        bool plus = !A && (Bflag || bx <= by);
        uint32_t Tg9 = plus ? (Bflag ? P.Tsearch9 : P.Tcap9)
                            : (A ? (Bflag ? 0u : P.Tback9) : P.Tminus9);

        uint32_t kg0 = plus ? P.k0[0] : P.k0[1];
        uint32_t kg1 = plus ? P.k1[0] : P.k1[1];
        uint32_t kf0 = plus ? P.k0[3] : P.k0[2];
        uint32_t kf1 = plus ? P.k1[3] : P.k1[2];

        uint32_t a, b;
        tf2x32(kg0, kg1, 0u, idx, a, b);           uint32_t abg = a ^ b;
        tf2x32(kf0, kf1, 0u, idx, a, b);           uint32_t abf = a ^ b;
        tf2x32(P.k0[4], P.k1[4], 0u, idx, a, b);   uint32_t abu = a ^ b;

        int wi = (int)wf[e];                       // weights are exact integers 0..7
        uint32_t TF9 = sTF9[(plus ? 8 : 0) + wi];

        bool fire = (abg < Tg9) && ((abf < TF9) || (abu < P.Tumin9));
        int nw = wi + (fire ? (plus ? 1 : -1) : 0);
        nw = min(max(nw, 0), 7);
        res[e] = (float)nw;
    }

    *reinterpret_cast<float4*>(out + i) = make_float4(res[0], res[1], res[2], res[3]);
}

static inline uint32_t thresh_from_prob(float p) {
    if (p <= 0.0f) return 0u;
    double v = ceil((double)p * 8388608.0);       // 2^23; u = m*2^-23 exactly, u<p <=> m<ceil(p*2^23)
    if (v < 0.0) return 0u;
    if (v > 4294967295.0) return 0xFFFFFFFFu;
    return (uint32_t)v;
}

static inline uint32_t shl9_clamp(uint32_t T) {
    uint64_t v = (uint64_t)T << 9;                // m<T <=> (o0^o1) < (T<<9); clamp p>=1.0 case
    return v > 0xFFFFFFFFull ? 0xFFFFFFFFu : (uint32_t)v;
}

extern "C" void kernel_launch(void* const* d_in, const int* in_sizes, int n_in,
                              void* d_out, int out_size) {
    const float* w    = (const float*)d_in[0];
    const int*   inS  = (const int*)d_in[1];
    const int*   outS = (const int*)d_in[2];

    Params P;
    // jax.random.key(42) -> data (0, 42); split(key, 5) fold-like: subkey_j = threefry((0,42),(0,j))
    for (int j = 0; j < 5; ++j)
        tf2x32(0u, 42u, 0u, (uint32_t)j, P.k0[j], P.k1[j]);

    P.Tcap9    = shl9_clamp(thresh_from_prob((float)0.102));
    P.Tminus9  = shl9_clamp(thresh_from_prob((float)0.051));
    P.Tsearch9 = shl9_clamp(thresh_from_prob((float)0.032));
    P.Tback9   = shl9_clamp(thresh_from_prob((float)0.96));
    P.Tumin9   = shl9_clamp(thresh_from_prob((float)0.008));

    const float inv7 = (float)(1.0 / 7.0);        // matches jnp f32(1.0/MAXW)
    for (int ww = 0; ww < 8; ++ww) {
        float rr = (float)ww * inv7;
        float a  = (1.0f - rr) * (1.0f + rr);     // F_minus prob
        float b  = rr * (2.0f - rr);              // F_plus prob
        P.TF9[ww]     = shl9_clamp(thresh_from_prob(a));
        P.TF9[8 + ww] = shl9_clamp(thresh_from_prob(b));
    }

    prep_kernel<<<(YTAB_N + XTAB_N + 255) / 256, 256>>>(inS, outS);
    stdp_main<<<N_ELEMS / 1024, 256>>>(w, (float*)d_out, P);
}

// round 3
// speedup vs baseline: 2.1522x; 1.5391x over previous
#include <cuda_runtime.h>
#include <cstdint>
#include <math.h>

// ModSTDP: bit-exact replay of JAX threefry2x32 (partitionable scheme) STDP update.
// weight shape (R,C,COUT,CIN,KH,KW) = (16,16,64,16,8,8) -> 16,777,216 f32 elements.
// STRIDE=0 => bx depends only on (ci,kh,kw) [1024 vals]; by on (o,r,c) [16384 vals].
//
// R3: two-phase stream compaction. fire = gate && (F || umin); gate fires for
// only ~8% of elements. Phase 1 does the gate draw only (1 threefry) + copies
// weights to out + compacts survivors into a fixed 256-slot-per-block list
// (each 1024-elem block has constant `by`; worst-case survivor mean ~111,
// so 256 slots is +15 sigma safe). Phase 2 does the remaining 2 draws for
// survivors only and scatters the +-1 updates.

#define N_ELEMS   16777216
#define XTAB_N    1024     // CIN*KH*KW
#define YTAB_N    16384    // COUT*R*C
#define NBLK      16384    // phase-1 blocks (1024 elements each)
#define SLOTS     256      // list slots per block

__device__ uint8_t  g_xtab[XTAB_N];
__device__ uint8_t  g_ytab[YTAB_N];
__device__ uint32_t g_list[NBLK * SLOTS];   // packed survivors: idx | wi<<24 | plus<<27
__device__ uint32_t g_cnt[NBLK];

struct Params {
    uint32_t k0[5], k1[5];                        // split(key(42),5) subkeys
    uint32_t Tsearch9, Tcap9, Tback9, Tminus9, Tumin9;  // thresholds << 9 (clamped)
    uint32_t TF9[16];                             // [0..7]=F_minus<<9, [8..15]=F_plus<<9
};

__host__ __device__ __forceinline__ uint32_t rotl32(uint32_t x, int r) {
    return (x << r) | (x >> (32 - r));
}

// Threefry-2x32, 20 rounds (Random123 / JAX threefry2x32_p)
__host__ __device__ __forceinline__ void tf2x32(uint32_t k0, uint32_t k1,
                                                uint32_t x0, uint32_t x1,
                                                uint32_t& o0, uint32_t& o1) {
    uint32_t ks2 = k0 ^ k1 ^ 0x1BD11BDAu;
    x0 += k0; x1 += k1;
#define TFR(r) { x0 += x1; x1 = rotl32(x1, r); x1 ^= x0; }
    TFR(13) TFR(15) TFR(26) TFR(6)   x0 += k1;  x1 += ks2 + 1u;
    TFR(17) TFR(29) TFR(16) TFR(24)  x0 += ks2; x1 += k0  + 2u;
    TFR(13) TFR(15) TFR(26) TFR(6)   x0 += k0;  x1 += k1  + 3u;
    TFR(17) TFR(29) TFR(16) TFR(24)  x0 += k1;  x1 += ks2 + 4u;
    TFR(13) TFR(15) TFR(26) TFR(6)   x0 += ks2; x1 += k0  + 5u;
#undef TFR
    o0 = x0; o1 = x1;
}

__global__ void __launch_bounds__(256) prep_kernel(const int* __restrict__ inS,
                                                   const int* __restrict__ outS) {
    int t = blockIdx.x * 256 + threadIdx.x;
    if (t < YTAB_N) {
        int s = 0;
#pragma unroll
        for (int tt = 0; tt < 7; ++tt) s += outS[tt * YTAB_N + t];
        g_ytab[t] = (uint8_t)(7 - s);
    } else if (t < YTAB_N + XTAB_N) {
        int u = t - YTAB_N;
        int s = 0;
#pragma unroll
        for (int tt = 0; tt < 7; ++tt) s += inS[tt * XTAB_N + u];
        g_xtab[u] = (uint8_t)(7 - s);
    }
}

// Phase 1: gate draw for every element; copy weights; compact survivors.
__global__ void __launch_bounds__(256) stdp_gate(const float* __restrict__ w,
                                                 float* __restrict__ out,
                                                 Params P) {
    __shared__ uint32_t s_cnt;
    if (threadIdx.x == 0) s_cnt = 0u;
    __syncthreads();

    uint32_t lane = threadIdx.x & 31u;
    uint32_t i = (blockIdx.x * 256u + threadIdx.x) * 4u;

    uint32_t khkw = i & 63u;
    uint32_t ci   = (i >> 6)  & 15u;
    uint32_t o    = (i >> 10) & 63u;
    uint32_t c    = (i >> 16) & 15u;
    uint32_t r    = (i >> 20) & 15u;

    uint32_t xword = *reinterpret_cast<const uint32_t*>(&g_xtab[ci * 64u + khkw]);
    uint32_t by    = g_ytab[o * 256u + r * 16u + c];
    bool Bflag = (by == 7u);

    float4 wv = *reinterpret_cast<const float4*>(w + i);
    // pass-through copy (weights already in [0,7]; clip is identity without fire)
    *reinterpret_cast<float4*>(out + i) = wv;
    float wf[4] = {wv.x, wv.y, wv.z, wv.w};

    uint32_t listbase = blockIdx.x * SLOTS;

#pragma unroll
    for (int e = 0; e < 4; ++e) {
        uint32_t idx = i + (uint32_t)e;
        uint32_t bx = (xword >> (8 * e)) & 0xFFu;

        bool A = (bx == 7u);
        bool plus = !A && (Bflag || bx <= by);
        uint32_t Tg9 = plus ? (Bflag ? P.Tsearch9 : P.Tcap9)
                            : (A ? (Bflag ? 0u : P.Tback9) : P.Tminus9);

        uint32_t kg0 = plus ? P.k0[0] : P.k0[1];
        uint32_t kg1 = plus ? P.k1[0] : P.k1[1];

        uint32_t a, b;
        tf2x32(kg0, kg1, 0u, idx, a, b);
        bool fire = (a ^ b) < Tg9;

        // warp-aggregated compaction into this block's fixed list segment
        uint32_t mask = __ballot_sync(0xFFFFFFFFu, fire);
        if (mask != 0u) {
            uint32_t leader = __ffs(mask) - 1u;
            uint32_t base = 0u;
            if (lane == leader) base = atomicAdd(&s_cnt, (uint32_t)__popc(mask));
            base = __shfl_sync(0xFFFFFFFFu, base, leader);
            if (fire) {
                uint32_t pos = base + (uint32_t)__popc(mask & ((1u << lane) - 1u));
                if (pos < SLOTS) {
                    uint32_t wi = (uint32_t)(int)wf[e];   // exact int 0..7
                    g_list[listbase + pos] = idx | (wi << 24) | ((plus ? 1u : 0u) << 27);
                }
            }
        }
    }

    __syncthreads();
    if (threadIdx.x == 0) g_cnt[blockIdx.x] = min(s_cnt, (uint32_t)SLOTS);
}

// Phase 2: F + umin draws for survivors only; scatter +-1 updates.
__global__ void __launch_bounds__(256) stdp_fire(float* __restrict__ out, Params P) {
    __shared__ uint32_t sTF9[16];
    __shared__ uint32_t s_n;
    if (threadIdx.x < 16) sTF9[threadIdx.x] = P.TF9[threadIdx.x];
    if (threadIdx.x == 0) s_n = g_cnt[blockIdx.x];
    __syncthreads();

    uint32_t t = threadIdx.x;
    if (t >= s_n) return;

    uint32_t entry = g_list[blockIdx.x * SLOTS + t];
    uint32_t idx  = entry & 0x00FFFFFFu;
    uint32_t wi   = (entry >> 24) & 7u;
    bool     plus = (entry >> 27) & 1u;

    uint32_t kf0 = plus ? P.k0[3] : P.k0[2];
    uint32_t kf1 = plus ? P.k1[3] : P.k1[2];

    uint32_t a, b;
    tf2x32(kf0, kf1, 0u, idx, a, b);          uint32_t abf = a ^ b;
    tf2x32(P.k0[4], P.k1[4], 0u, idx, a, b);  uint32_t abu = a ^ b;

    uint32_t TF9 = sTF9[(plus ? 8u : 0u) + wi];
    bool fire = (abf < TF9) || (abu < P.Tumin9);
    if (fire) {
        int nw = (int)wi + (plus ? 1 : -1);
        nw = min(max(nw, 0), 7);
        out[idx] = (float)nw;
    }
}

static inline uint32_t thresh_from_prob(float p) {
    if (p <= 0.0f) return 0u;
    double v = ceil((double)p * 8388608.0);       // 2^23; u=m*2^-23 exactly; u<p <=> m<ceil(p*2^23)
    if (v < 0.0) return 0u;
    if (v > 4294967295.0) return 0xFFFFFFFFu;
    return (uint32_t)v;
}

static inline uint32_t shl9_clamp(uint32_t T) {
    uint64_t v = (uint64_t)T << 9;                // m<T <=> (o0^o1) < (T<<9); clamp p>=1.0
    return v > 0xFFFFFFFFull ? 0xFFFFFFFFu : (uint32_t)v;
}

extern "C" void kernel_launch(void* const* d_in, const int* in_sizes, int n_in,
                              void* d_out, int out_size) {
    const float* w    = (const float*)d_in[0];
    const int*   inS  = (const int*)d_in[1];
    const int*   outS = (const int*)d_in[2];

    Params P;
    for (int j = 0; j < 5; ++j)
        tf2x32(0u, 42u, 0u, (uint32_t)j, P.k0[j], P.k1[j]);

    P.Tcap9    = shl9_clamp(thresh_from_prob((float)0.102));
    P.Tminus9  = shl9_clamp(thresh_from_prob((float)0.051));
    P.Tsearch9 = shl9_clamp(thresh_from_prob((float)0.032));
    P.Tback9   = shl9_clamp(thresh_from_prob((float)0.96));
    P.Tumin9   = shl9_clamp(thresh_from_prob((float)0.008));

    const float inv7 = (float)(1.0 / 7.0);
    for (int ww = 0; ww < 8; ++ww) {
        float rr = (float)ww * inv7;
        float a  = (1.0f - rr) * (1.0f + rr);     // F_minus prob
        float b  = rr * (2.0f - rr);              // F_plus prob
        P.TF9[ww]     = shl9_clamp(thresh_from_prob(a));
        P.TF9[8 + ww] = shl9_clamp(thresh_from_prob(b));
    }

    prep_kernel<<<(YTAB_N + XTAB_N + 255) / 256, 256>>>(inS, outS);
    stdp_gate<<<NBLK, 256>>>(w, (float*)d_out, P);
    stdp_fire<<<NBLK, 256>>>((float*)d_out, P);
}

// round 5
// speedup vs baseline: 2.4103x; 1.1199x over previous
#include <cuda_runtime.h>
#include <cstdint>
#include <math.h>

// ModSTDP: bit-exact replay of JAX threefry2x32 (partitionable scheme) STDP update.
// weight shape (R,C,COUT,CIN,KH,KW) = (16,16,64,16,8,8) -> 16,777,216 f32 elements.
// STRIDE=0 => bx depends only on (ci,kh,kw) [1024 vals]; by on (o,r,c) [16384 vals].
//
// R4 (resubmit after infra failure): (a) compute the 4 independent gate
// threefry chains up-front (ILP=4), compact once afterwards with a shfl
// prefix-scan (no per-element ballots); (b) force threefry round-adds onto
// the IMAD/fma pipe via mad.lo with a runtime-opaque multiplier; (c) prune
// clamp-no-op survivors (minus@w=0, plus@w=7) from the phase-2 list.

#define N_ELEMS   16777216
#define XTAB_N    1024     // CIN*KH*KW
#define YTAB_N    16384    // COUT*R*C
#define NBLK      16384    // phase-1 blocks (1024 elements each)
#define SLOTS     256      // list slots per block

__device__ uint8_t  g_xtab[XTAB_N];
__device__ uint8_t  g_ytab[YTAB_N];
__device__ uint32_t g_list[NBLK * SLOTS];   // packed survivors: idx | wi<<24 | plus<<27
__device__ uint32_t g_cnt[NBLK];

struct Params {
    uint32_t k0[5], k1[5];                        // split(key(42),5) subkeys
    uint32_t Tsearch9, Tcap9, Tback9, Tminus9, Tumin9;  // thresholds << 9 (clamped)
    uint32_t TF9[16];                             // [0..7]=F_minus<<9, [8..15]=F_plus<<9
    uint32_t one;                                 // runtime 1 (opaque to ptxas) for mad.lo
};

__host__ __device__ __forceinline__ uint32_t rotl32(uint32_t x, int r) {
    return (x << r) | (x >> (32 - r));
}

// add on the IMAD (fma) pipe: a*one + b with one==1 at runtime
__device__ __forceinline__ uint32_t addI(uint32_t a, uint32_t one, uint32_t b) {
    uint32_t r;
    asm("mad.lo.u32 %0, %1, %2, %3;" : "=r"(r) : "r"(a), "r"(one), "r"(b));
    return r;
}

// Threefry-2x32, 20 rounds — device variant, round-adds on IMAD pipe
__device__ __forceinline__ void tf2x32_dev(uint32_t k0, uint32_t k1,
                                           uint32_t x1in, uint32_t one,
                                           uint32_t& o0, uint32_t& o1) {
    uint32_t ks2 = k0 ^ k1 ^ 0x1BD11BDAu;
    uint32_t x0 = k0;            // x0 starts at 0 + k0
    uint32_t x1 = x1in + k1;
#define TFR(r) { x0 = addI(x0, one, x1); x1 = rotl32(x1, r); x1 ^= x0; }
    TFR(13) TFR(15) TFR(26) TFR(6)   x0 += k1;  x1 += ks2 + 1u;
    TFR(17) TFR(29) TFR(16) TFR(24)  x0 += ks2; x1 += k0  + 2u;
    TFR(13) TFR(15) TFR(26) TFR(6)   x0 += k0;  x1 += k1  + 3u;
    TFR(17) TFR(29) TFR(16) TFR(24)  x0 += k1;  x1 += ks2 + 4u;
    TFR(13) TFR(15) TFR(26) TFR(6)   x0 += ks2; x1 += k0  + 5u;
#undef TFR
    o0 = x0; o1 = x1;
}

// Host variant (plain adds) for subkey derivation
static inline void tf2x32_host(uint32_t k0, uint32_t k1,
                               uint32_t x0, uint32_t x1,
                               uint32_t& o0, uint32_t& o1) {
    auto rot = [](uint32_t x, int r) { return (x << r) | (x >> (32 - r)); };
    uint32_t ks2 = k0 ^ k1 ^ 0x1BD11BDAu;
    x0 += k0; x1 += k1;
#define TFRH(r) { x0 += x1; x1 = rot(x1, r); x1 ^= x0; }
    TFRH(13) TFRH(15) TFRH(26) TFRH(6)   x0 += k1;  x1 += ks2 + 1u;
    TFRH(17) TFRH(29) TFRH(16) TFRH(24)  x0 += ks2; x1 += k0  + 2u;
    TFRH(13) TFRH(15) TFRH(26) TFRH(6)   x0 += k0;  x1 += k1  + 3u;
    TFRH(17) TFRH(29) TFRH(16) TFRH(24)  x0 += k1;  x1 += ks2 + 4u;
    TFRH(13) TFRH(15) TFRH(26) TFRH(6)   x0 += ks2; x1 += k0  + 5u;
#undef TFRH
    o0 = x0; o1 = x1;
}

__global__ void __launch_bounds__(256) prep_kernel(const int* __restrict__ inS,
                                                   const int* __restrict__ outS) {
    int t = blockIdx.x * 256 + threadIdx.x;
    if (t < YTAB_N) {
        int s = 0;
#pragma unroll
        for (int tt = 0; tt < 7; ++tt) s += outS[tt * YTAB_N + t];
        g_ytab[t] = (uint8_t)(7 - s);
    } else if (t < YTAB_N + XTAB_N) {
        int u = t - YTAB_N;
        int s = 0;
#pragma unroll
        for (int tt = 0; tt < 7; ++tt) s += inS[tt * XTAB_N + u];
        g_xtab[u] = (uint8_t)(7 - s);
    }
}

// Phase 1: gate draw for every element; copy weights; compact survivors.
__global__ void __launch_bounds__(256) stdp_gate(const float* __restrict__ w,
                                                 float* __restrict__ out,
                                                 Params P) {
    __shared__ uint32_t s_cnt;
    if (threadIdx.x == 0) s_cnt = 0u;
    __syncthreads();

    uint32_t lane = threadIdx.x & 31u;
    uint32_t i = (blockIdx.x * 256u + threadIdx.x) * 4u;

    uint32_t khkw = i & 63u;
    uint32_t ci   = (i >> 6)  & 15u;
    uint32_t o    = (i >> 10) & 63u;
    uint32_t c    = (i >> 16) & 15u;
    uint32_t r    = (i >> 20) & 15u;

    uint32_t xword = *reinterpret_cast<const uint32_t*>(&g_xtab[ci * 64u + khkw]);
    uint32_t by    = g_ytab[o * 256u + r * 16u + c];
    bool Bflag = (by == 7u);

    float4 wv = *reinterpret_cast<const float4*>(w + i);
    *reinterpret_cast<float4*>(out + i) = wv;   // pass-through; fired elems patched in phase 2
    float wf[4] = {wv.x, wv.y, wv.z, wv.w};

    // ---- per-element branch classification (no RNG yet) ----
    bool plusA[4];
    uint32_t Tg9A[4], wiA[4];
#pragma unroll
    for (int e = 0; e < 4; ++e) {
        uint32_t bx = (xword >> (8 * e)) & 0xFFu;
        bool A = (bx == 7u);
        bool plus = !A && (Bflag || bx <= by);
        plusA[e] = plus;
        Tg9A[e] = plus ? (Bflag ? P.Tsearch9 : P.Tcap9)
                       : (A ? (Bflag ? 0u : P.Tback9) : P.Tminus9);
        wiA[e] = (uint32_t)(int)wf[e];          // exact int 0..7
    }

    // ---- 4 independent threefry chains, no sync points between ----
    bool fire[4];
#pragma unroll
    for (int e = 0; e < 4; ++e) {
        uint32_t kg0 = plusA[e] ? P.k0[0] : P.k0[1];
        uint32_t kg1 = plusA[e] ? P.k1[0] : P.k1[1];
        uint32_t a, b;
        tf2x32_dev(kg0, kg1, i + (uint32_t)e, P.one, a, b);
        bool f = (a ^ b) < Tg9A[e];
        // clamp no-ops never need phase 2: minus@w=0 and plus@w=7 store the same value
        bool noop = plusA[e] ? (wiA[e] == 7u) : (wiA[e] == 0u);
        fire[e] = f && !noop;
    }

    // ---- single compaction: shfl inclusive scan of per-thread counts ----
    uint32_t nf = (uint32_t)fire[0] + (uint32_t)fire[1] +
                  (uint32_t)fire[2] + (uint32_t)fire[3];
    uint32_t incl = nf;
#pragma unroll
    for (int d = 1; d < 32; d <<= 1) {
        uint32_t v = __shfl_up_sync(0xFFFFFFFFu, incl, d);
        if (lane >= (uint32_t)d) incl += v;
    }
    uint32_t wtot = __shfl_sync(0xFFFFFFFFu, incl, 31);
    uint32_t wbase = 0u;
    if (lane == 0 && wtot) wbase = atomicAdd(&s_cnt, wtot);
    wbase = __shfl_sync(0xFFFFFFFFu, wbase, 0);

    uint32_t pos = wbase + (incl - nf);
    uint32_t listbase = blockIdx.x * SLOTS;
#pragma unroll
    for (int e = 0; e < 4; ++e) {
        if (fire[e]) {
            if (pos < SLOTS)
                g_list[listbase + pos] =
                    (i + (uint32_t)e) | (wiA[e] << 24) | ((plusA[e] ? 1u : 0u) << 27);
            pos++;
        }
    }

    __syncthreads();
    if (threadIdx.x == 0) g_cnt[blockIdx.x] = min(s_cnt, (uint32_t)SLOTS);
}

// Phase 2: F + umin draws for survivors only; scatter +-1 updates.
__global__ void __launch_bounds__(256) stdp_fire(float* __restrict__ out, Params P) {
    __shared__ uint32_t sTF9[16];
    __shared__ uint32_t s_n;
    if (threadIdx.x < 16) sTF9[threadIdx.x] = P.TF9[threadIdx.x];
    if (threadIdx.x == 0) s_n = g_cnt[blockIdx.x];
    __syncthreads();

    uint32_t t = threadIdx.x;
    if (t >= s_n) return;

    uint32_t entry = g_list[blockIdx.x * SLOTS + t];
    uint32_t idx  = entry & 0x00FFFFFFu;
    uint32_t wi   = (entry >> 24) & 7u;
    bool     plus = (entry >> 27) & 1u;

    uint32_t kf0 = plus ? P.k0[3] : P.k0[2];
    uint32_t kf1 = plus ? P.k1[3] : P.k1[2];

    uint32_t a, b;
    tf2x32_dev(kf0, kf1, idx, P.one, a, b);          uint32_t abf = a ^ b;
    tf2x32_dev(P.k0[4], P.k1[4], idx, P.one, a, b);  uint32_t abu = a ^ b;

    uint32_t TF9 = sTF9[(plus ? 8u : 0u) + wi];
    bool doit = (abf < TF9) || (abu < P.Tumin9);
    if (doit) {
        int nw = (int)wi + (plus ? 1 : -1);
        nw = min(max(nw, 0), 7);                     // unreachable clamp kept for safety
        out[idx] = (float)nw;
    }
}

static inline uint32_t thresh_from_prob(float p) {
    if (p <= 0.0f) return 0u;
    double v = ceil((double)p * 8388608.0);          // 2^23; u=m*2^-23 exactly
    if (v < 0.0) return 0u;
    if (v > 4294967295.0) return 0xFFFFFFFFu;
    return (uint32_t)v;
}

static inline uint32_t shl9_clamp(uint32_t T) {
    uint64_t v = (uint64_t)T << 9;                   // m<T <=> (o0^o1) < (T<<9)
    return v > 0xFFFFFFFFull ? 0xFFFFFFFFu : (uint32_t)v;
}

extern "C" void kernel_launch(void* const* d_in, const int* in_sizes, int n_in,
                              void* d_out, int out_size) {
    const float* w    = (const float*)d_in[0];
    const int*   inS  = (const int*)d_in[1];
    const int*   outS = (const int*)d_in[2];

    Params P;
    for (int j = 0; j < 5; ++j)
        tf2x32_host(0u, 42u, 0u, (uint32_t)j, P.k0[j], P.k1[j]);

    P.Tcap9    = shl9_clamp(thresh_from_prob((float)0.102));
    P.Tminus9  = shl9_clamp(thresh_from_prob((float)0.051));
    P.Tsearch9 = shl9_clamp(thresh_from_prob((float)0.032));
    P.Tback9   = shl9_clamp(thresh_from_prob((float)0.96));
    P.Tumin9   = shl9_clamp(thresh_from_prob((float)0.008));

    const float inv7 = (float)(1.0 / 7.0);
    for (int ww = 0; ww < 8; ++ww) {
        float rr = (float)ww * inv7;
        float a  = (1.0f - rr) * (1.0f + rr);        // F_minus prob
        float b  = rr * (2.0f - rr);                 // F_plus prob
        P.TF9[ww]     = shl9_clamp(thresh_from_prob(a));
        P.TF9[8 + ww] = shl9_clamp(thresh_from_prob(b));
    }
    P.one = 1u;

    prep_kernel<<<(YTAB_N + XTAB_N + 255) / 256, 256>>>(inS, outS);
    stdp_gate<<<NBLK, 256>>>(w, (float*)d_out, P);
    stdp_fire<<<NBLK, 256>>>((float*)d_out, P);
}

// round 6
// speedup vs baseline: 2.4149x; 1.0019x over previous
#include <cuda_runtime.h>
#include <cstdint>
#include <math.h>

// ModSTDP: bit-exact replay of JAX threefry2x32 (partitionable scheme) STDP update.
// weight shape (R,C,COUT,CIN,KH,KW) = (16,16,64,16,8,8) -> 16,777,216 f32 elements.
// STRIDE=0 => bx depends only on (ci,kh,kw) [1024 vals]; by on (o,r,c) [16384 vals].
//
// R6: force single-instruction rotations via __funnelshift_l (empirically the
// C++ rotate idiom was costing ~3 alu ops/round -> ~20 extra alu per threefry).
// Round-adds stay on the IMAD/fma pipe (runtime-opaque mad.lo). Structure
// (two-phase compaction, clamp-noop pruning) unchanged from R4/R5.

#define N_ELEMS   16777216
#define XTAB_N    1024     // CIN*KH*KW
#define YTAB_N    16384    // COUT*R*C
#define NBLK      16384    // phase-1 blocks (1024 elements each)
#define SLOTS     256      // list slots per block

__device__ uint8_t  g_xtab[XTAB_N];
__device__ uint8_t  g_ytab[YTAB_N];
__device__ uint32_t g_list[NBLK * SLOTS];   // packed survivors: idx | wi<<24 | plus<<27
__device__ uint32_t g_cnt[NBLK];

struct Params {
    uint32_t k0[5], k1[5];                        // split(key(42),5) subkeys
    uint32_t Tsearch9, Tcap9, Tback9, Tminus9, Tumin9;  // thresholds << 9 (clamped)
    uint32_t TF9[16];                             // [0..7]=F_minus<<9, [8..15]=F_plus<<9
    uint32_t one;                                 // runtime 1 (opaque to ptxas) for mad.lo
};

// add on the IMAD (fma) pipe: a*one + b with one==1 at runtime
__device__ __forceinline__ uint32_t addI(uint32_t a, uint32_t one, uint32_t b) {
    uint32_t r;
    asm("mad.lo.u32 %0, %1, %2, %3;" : "=r"(r) : "r"(a), "r"(one), "r"(b));
    return r;
}

// Threefry-2x32, 20 rounds — device variant:
// rotation = single funnel-shift SHF; round-adds on IMAD pipe.
__device__ __forceinline__ void tf2x32_dev(uint32_t k0, uint32_t k1,
                                           uint32_t x1in, uint32_t one,
                                           uint32_t& o0, uint32_t& o1) {
    uint32_t ks2 = k0 ^ k1 ^ 0x1BD11BDAu;
    uint32_t x0 = k0;            // x0 starts at 0 + k0
    uint32_t x1 = x1in + k1;
#define TFR(r) { x0 = addI(x0, one, x1); x1 = __funnelshift_l(x1, x1, r); x1 ^= x0; }
    TFR(13) TFR(15) TFR(26) TFR(6)   x0 += k1;  x1 += ks2 + 1u;
    TFR(17) TFR(29) TFR(16) TFR(24)  x0 += ks2; x1 += k0  + 2u;
    TFR(13) TFR(15) TFR(26) TFR(6)   x0 += k0;  x1 += k1  + 3u;
    TFR(17) TFR(29) TFR(16) TFR(24)  x0 += k1;  x1 += ks2 + 4u;
    TFR(13) TFR(15) TFR(26) TFR(6)   x0 += ks2; x1 += k0  + 5u;
#undef TFR
    o0 = x0; o1 = x1;
}

// Host variant (plain adds) for subkey derivation
static inline void tf2x32_host(uint32_t k0, uint32_t k1,
                               uint32_t x0, uint32_t x1,
                               uint32_t& o0, uint32_t& o1) {
    auto rot = [](uint32_t x, int r) { return (x << r) | (x >> (32 - r)); };
    uint32_t ks2 = k0 ^ k1 ^ 0x1BD11BDAu;
    x0 += k0; x1 += k1;
#define TFRH(r) { x0 += x1; x1 = rot(x1, r); x1 ^= x0; }
    TFRH(13) TFRH(15) TFRH(26) TFRH(6)   x0 += k1;  x1 += ks2 + 1u;
    TFRH(17) TFRH(29) TFRH(16) TFRH(24)  x0 += ks2; x1 += k0  + 2u;
    TFRH(13) TFRH(15) TFRH(26) TFRH(6)   x0 += k0;  x1 += k1  + 3u;
    TFRH(17) TFRH(29) TFRH(16) TFRH(24)  x0 += k1;  x1 += ks2 + 4u;
    TFRH(13) TFRH(15) TFRH(26) TFRH(6)   x0 += ks2; x1 += k0  + 5u;
#undef TFRH
    o0 = x0; o1 = x1;
}

__global__ void __launch_bounds__(256) prep_kernel(const int* __restrict__ inS,
                                                   const int* __restrict__ outS) {
    int t = blockIdx.x * 256 + threadIdx.x;
    if (t < YTAB_N) {
        int s = 0;
#pragma unroll
        for (int tt = 0; tt < 7; ++tt) s += outS[tt * YTAB_N + t];
        g_ytab[t] = (uint8_t)(7 - s);
    } else if (t < YTAB_N + XTAB_N) {
        int u = t - YTAB_N;
        int s = 0;
#pragma unroll
        for (int tt = 0; tt < 7; ++tt) s += inS[tt * XTAB_N + u];
        g_xtab[u] = (uint8_t)(7 - s);
    }
}

// Phase 1: gate draw for every element; copy weights; compact survivors.
__global__ void __launch_bounds__(256) stdp_gate(const float* __restrict__ w,
                                                 float* __restrict__ out,
                                                 Params P) {
    __shared__ uint32_t s_cnt;
    if (threadIdx.x == 0) s_cnt = 0u;
    __syncthreads();

    uint32_t lane = threadIdx.x & 31u;
    uint32_t i = (blockIdx.x * 256u + threadIdx.x) * 4u;

    uint32_t khkw = i & 63u;
    uint32_t ci   = (i >> 6)  & 15u;
    uint32_t o    = (i >> 10) & 63u;
    uint32_t c    = (i >> 16) & 15u;
    uint32_t r    = (i >> 20) & 15u;

    uint32_t xword = *reinterpret_cast<const uint32_t*>(&g_xtab[ci * 64u + khkw]);
    uint32_t by    = g_ytab[o * 256u + r * 16u + c];
    bool Bflag = (by == 7u);

    float4 wv = *reinterpret_cast<const float4*>(w + i);
    *reinterpret_cast<float4*>(out + i) = wv;   // pass-through; fired elems patched in phase 2
    float wf[4] = {wv.x, wv.y, wv.z, wv.w};

    // ---- per-element branch classification (no RNG yet) ----
    bool plusA[4];
    uint32_t Tg9A[4], wiA[4];
#pragma unroll
    for (int e = 0; e < 4; ++e) {
        uint32_t bx = (xword >> (8 * e)) & 0xFFu;
        bool A = (bx == 7u);
        bool plus = !A && (Bflag || bx <= by);
        plusA[e] = plus;
        Tg9A[e] = plus ? (Bflag ? P.Tsearch9 : P.Tcap9)
                       : (A ? (Bflag ? 0u : P.Tback9) : P.Tminus9);
        wiA[e] = (uint32_t)(int)wf[e];          // exact int 0..7
    }

    // ---- 4 independent threefry chains, no sync points between ----
    bool fire[4];
#pragma unroll
    for (int e = 0; e < 4; ++e) {
        uint32_t kg0 = plusA[e] ? P.k0[0] : P.k0[1];
        uint32_t kg1 = plusA[e] ? P.k1[0] : P.k1[1];
        uint32_t a, b;
        tf2x32_dev(kg0, kg1, i + (uint32_t)e, P.one, a, b);
        bool f = (a ^ b) < Tg9A[e];
        // clamp no-ops never need phase 2: minus@w=0 and plus@w=7 store the same value
        bool noop = plusA[e] ? (wiA[e] == 7u) : (wiA[e] == 0u);
        fire[e] = f && !noop;
    }

    // ---- single compaction: shfl inclusive scan of per-thread counts ----
    uint32_t nf = (uint32_t)fire[0] + (uint32_t)fire[1] +
                  (uint32_t)fire[2] + (uint32_t)fire[3];
    uint32_t incl = nf;
#pragma unroll
    for (int d = 1; d < 32; d <<= 1) {
        uint32_t v = __shfl_up_sync(0xFFFFFFFFu, incl, d);
        if (lane >= (uint32_t)d) incl += v;
    }
    uint32_t wtot = __shfl_sync(0xFFFFFFFFu, incl, 31);
    uint32_t wbase = 0u;
    if (lane == 0 && wtot) wbase = atomicAdd(&s_cnt, wtot);
    wbase = __shfl_sync(0xFFFFFFFFu, wbase, 0);

    uint32_t pos = wbase + (incl - nf);
    uint32_t listbase = blockIdx.x * SLOTS;
#pragma unroll
    for (int e = 0; e < 4; ++e) {
        if (fire[e]) {
            if (pos < SLOTS)
                g_list[listbase + pos] =
                    (i + (uint32_t)e) | (wiA[e] << 24) | ((plusA[e] ? 1u : 0u) << 27);
            pos++;
        }
    }

    __syncthreads();
    if (threadIdx.x == 0) g_cnt[blockIdx.x] = min(s_cnt, (uint32_t)SLOTS);
}

// Phase 2: F + umin draws for survivors only; scatter +-1 updates.
__global__ void __launch_bounds__(256) stdp_fire(float* __restrict__ out, Params P) {
    __shared__ uint32_t sTF9[16];
    __shared__ uint32_t s_n;
    if (threadIdx.x < 16) sTF9[threadIdx.x] = P.TF9[threadIdx.x];
    if (threadIdx.x == 0) s_n = g_cnt[blockIdx.x];
    __syncthreads();

    uint32_t t = threadIdx.x;
    if (t >= s_n) return;

    uint32_t entry = g_list[blockIdx.x * SLOTS + t];
    uint32_t idx  = entry & 0x00FFFFFFu;
    uint32_t wi   = (entry >> 24) & 7u;
    bool     plus = (entry >> 27) & 1u;

    uint32_t kf0 = plus ? P.k0[3] : P.k0[2];
    uint32_t kf1 = plus ? P.k1[3] : P.k1[2];

    uint32_t a, b;
    tf2x32_dev(kf0, kf1, idx, P.one, a, b);          uint32_t abf = a ^ b;
    tf2x32_dev(P.k0[4], P.k1[4], idx, P.one, a, b);  uint32_t abu = a ^ b;

    uint32_t TF9 = sTF9[(plus ? 8u : 0u) + wi];
    bool doit = (abf < TF9) || (abu < P.Tumin9);
    if (doit) {
        int nw = (int)wi + (plus ? 1 : -1);
        nw = min(max(nw, 0), 7);                     // unreachable clamp kept for safety
        out[idx] = (float)nw;
    }
}

static inline uint32_t thresh_from_prob(float p) {
    if (p <= 0.0f) return 0u;
    double v = ceil((double)p * 8388608.0);          // 2^23; u=m*2^-23 exactly
    if (v < 0.0) return 0u;
    if (v > 4294967295.0) return 0xFFFFFFFFu;
    return (uint32_t)v;
}

static inline uint32_t shl9_clamp(uint32_t T) {
    uint64_t v = (uint64_t)T << 9;                   // m<T <=> (o0^o1) < (T<<9)
    return v > 0xFFFFFFFFull ? 0xFFFFFFFFu : (uint32_t)v;
}

extern "C" void kernel_launch(void* const* d_in, const int* in_sizes, int n_in,
                              void* d_out, int out_size) {
    const float* w    = (const float*)d_in[0];
    const int*   inS  = (const int*)d_in[1];
    const int*   outS = (const int*)d_in[2];

    Params P;
    for (int j = 0; j < 5; ++j)
        tf2x32_host(0u, 42u, 0u, (uint32_t)j, P.k0[j], P.k1[j]);

    P.Tcap9    = shl9_clamp(thresh_from_prob((float)0.102));
    P.Tminus9  = shl9_clamp(thresh_from_prob((float)0.051));
    P.Tsearch9 = shl9_clamp(thresh_from_prob((float)0.032));
    P.Tback9   = shl9_clamp(thresh_from_prob((float)0.96));
    P.Tumin9   = shl9_clamp(thresh_from_prob((float)0.008));

    const float inv7 = (float)(1.0 / 7.0);
    for (int ww = 0; ww < 8; ++ww) {
        float rr = (float)ww * inv7;
        float a  = (1.0f - rr) * (1.0f + rr);        // F_minus prob
        float b  = rr * (2.0f - rr);                 // F_plus prob
        P.TF9[ww]     = shl9_clamp(thresh_from_prob(a));
        P.TF9[8 + ww] = shl9_clamp(thresh_from_prob(b));
    }
    P.one = 1u;

    prep_kernel<<<(YTAB_N + XTAB_N + 255) / 256, 256>>>(inS, outS);
    stdp_gate<<<NBLK, 256>>>(w, (float*)d_out, P);
    stdp_fire<<<NBLK, 256>>>((float*)d_out, P);
}

// round 7
// speedup vs baseline: 2.6891x; 1.1136x over previous
#include <cuda_runtime.h>
#include <cstdint>
#include <math.h>

// ModSTDP: bit-exact replay of JAX threefry2x32 (partitionable scheme) STDP update.
// weight shape (R,C,COUT,CIN,KH,KW) = (16,16,64,16,8,8) -> 16,777,216 f32 elements.
// STRIDE=0 => bx depends only on (ci,kh,kw) [1024 vals]; by on (o,r,c) [16384 vals].
//
// R7: strip non-threefry alu work. Per-block smem LUT indexed by bx gives
// {Tg9, kg0, kg1, ks2} (ks2 precomputed -> no per-call XORs, no key SELs, no
// branch compares). All adds (round + key-injection) forced onto the IMAD/fma
// pipe via runtime-opaque mad.lo. Gate does zero F2I: noop test is a bit
// compare of the weight float; phase 2 re-reads out[idx] for wi. 8 elems per
// thread, 128-thread blocks (one `by` group per block).

#define N_ELEMS   16777216
#define XTAB_N    1024     // CIN*KH*KW
#define YTAB_N    16384    // COUT*R*C
#define NBLK      16384    // phase-1 blocks (1024 elements each)
#define SLOTS     256      // list slots per block

__device__ uint8_t  g_xtab[XTAB_N];
__device__ uint8_t  g_ytab[YTAB_N];
__device__ uint32_t g_list[NBLK * SLOTS];   // packed survivors: idx | plus<<27
__device__ uint32_t g_cnt[NBLK];

struct Params {
    uint32_t k0[5], k1[5], ks2[5];                // subkeys + precomputed ks2
    uint32_t Tsearch9, Tcap9, Tback9, Tminus9, Tumin9;  // thresholds << 9
    uint32_t TF9[16];                             // [0..7]=F_minus<<9, [8..15]=F_plus<<9
    uint32_t one;                                 // runtime 1 (opaque to ptxas) for mad.lo
};

// add on the IMAD (fma) pipe: a*one + b with one==1 at runtime
__device__ __forceinline__ uint32_t addI(uint32_t a, uint32_t one, uint32_t b) {
    uint32_t r;
    asm("mad.lo.u32 %0, %1, %2, %3;" : "=r"(r) : "r"(a), "r"(one), "r"(b));
    return r;
}

// Threefry-2x32, 20 rounds. ks2 precomputed; ALL adds on IMAD pipe.
// alu pipe sees only 20 SHF + 20 LOP3.
__device__ __forceinline__ void tf2x32_lut(uint32_t k0, uint32_t k1, uint32_t ks2,
                                           uint32_t idx, uint32_t one,
                                           uint32_t& o0, uint32_t& o1) {
    uint32_t ks2p1 = addI(ks2, one, 1u);
    uint32_t k0p2  = addI(k0,  one, 2u);
    uint32_t k1p3  = addI(k1,  one, 3u);
    uint32_t ks2p4 = addI(ks2, one, 4u);
    uint32_t k0p5  = addI(k0,  one, 5u);
    uint32_t x0 = k0;                 // 0 + k0
    uint32_t x1 = addI(idx, one, k1);
#define TFR(r) { x0 = addI(x0, one, x1); x1 = __funnelshift_l(x1, x1, r); x1 ^= x0; }
    TFR(13) TFR(15) TFR(26) TFR(6)   x0 = addI(x0, one, k1);  x1 = addI(x1, one, ks2p1);
    TFR(17) TFR(29) TFR(16) TFR(24)  x0 = addI(x0, one, ks2); x1 = addI(x1, one, k0p2);
    TFR(13) TFR(15) TFR(26) TFR(6)   x0 = addI(x0, one, k0);  x1 = addI(x1, one, k1p3);
    TFR(17) TFR(29) TFR(16) TFR(24)  x0 = addI(x0, one, k1);  x1 = addI(x1, one, ks2p4);
    TFR(13) TFR(15) TFR(26) TFR(6)   x0 = addI(x0, one, ks2); x1 = addI(x1, one, k0p5);
#undef TFR
    o0 = x0; o1 = x1;
}

// Host variant for subkey derivation
static inline void tf2x32_host(uint32_t k0, uint32_t k1,
                               uint32_t x0, uint32_t x1,
                               uint32_t& o0, uint32_t& o1) {
    auto rot = [](uint32_t x, int r) { return (x << r) | (x >> (32 - r)); };
    uint32_t ks2 = k0 ^ k1 ^ 0x1BD11BDAu;
    x0 += k0; x1 += k1;
#define TFRH(r) { x0 += x1; x1 = rot(x1, r); x1 ^= x0; }
    TFRH(13) TFRH(15) TFRH(26) TFRH(6)   x0 += k1;  x1 += ks2 + 1u;
    TFRH(17) TFRH(29) TFRH(16) TFRH(24)  x0 += ks2; x1 += k0  + 2u;
    TFRH(13) TFRH(15) TFRH(26) TFRH(6)   x0 += k0;  x1 += k1  + 3u;
    TFRH(17) TFRH(29) TFRH(16) TFRH(24)  x0 += k1;  x1 += ks2 + 4u;
    TFRH(13) TFRH(15) TFRH(26) TFRH(6)   x0 += ks2; x1 += k0  + 5u;
#undef TFRH
    o0 = x0; o1 = x1;
}

__global__ void __launch_bounds__(256) prep_kernel(const int* __restrict__ inS,
                                                   const int* __restrict__ outS) {
    int t = blockIdx.x * 256 + threadIdx.x;
    if (t < YTAB_N) {
        int s = 0;
#pragma unroll
        for (int tt = 0; tt < 7; ++tt) s += outS[tt * YTAB_N + t];
        g_ytab[t] = (uint8_t)(7 - s);
    } else if (t < YTAB_N + XTAB_N) {
        int u = t - YTAB_N;
        int s = 0;
#pragma unroll
        for (int tt = 0; tt < 7; ++tt) s += inS[tt * XTAB_N + u];
        g_xtab[u] = (uint8_t)(7 - s);
    }
}

// Phase 1: gate draw for every element; copy weights; compact survivors.
// 128 threads x 8 elements = 1024 elements/block = one (r,c,o) group.
__global__ void __launch_bounds__(128) stdp_gate(const float* __restrict__ w,
                                                 float* __restrict__ out,
                                                 Params P) {
    __shared__ uint4    sL[8];    // per-bx: {Tg9, kg0, kg1, ks2}
    __shared__ uint2    sLb[8];   // per-bx: {noop weight bits, plusbit<<27}
    __shared__ uint32_t s_cnt;

    uint32_t tid = threadIdx.x, lane = tid & 31u, blk = blockIdx.x;
    if (tid == 0) s_cnt = 0u;
    if (tid < 8) {
        uint32_t o = blk & 63u, c = (blk >> 6) & 15u, r = (blk >> 10) & 15u;
        uint32_t by = g_ytab[o * 256u + r * 16u + c];
        bool B = (by == 7u);
        uint32_t bx = tid;
        bool A = (bx == 7u);
        bool plus = !A && (B || bx <= by);
        uint32_t Tg9 = plus ? (B ? P.Tsearch9 : P.Tcap9)
                            : (A ? (B ? 0u : P.Tback9) : P.Tminus9);
        int ks = plus ? 0 : 1;
        sL[bx]  = make_uint4(Tg9, P.k0[ks], P.k1[ks], P.ks2[ks]);
        sLb[bx] = make_uint2(plus ? 0x40E00000u : 0u,   // 7.0f : 0.0f bit patterns
                             (plus ? 1u : 0u) << 27);
    }
    __syncthreads();

    uint32_t i0 = blk * 1024u + tid * 8u;
    uint32_t khkw = i0 & 63u, ci = (i0 >> 6) & 15u;
    uint2 xw = *reinterpret_cast<const uint2*>(&g_xtab[ci * 64u + khkw]); // 8 bx bytes

    float4 w0 = *reinterpret_cast<const float4*>(w + i0);
    float4 w1 = *reinterpret_cast<const float4*>(w + i0 + 4);
    *reinterpret_cast<float4*>(out + i0)     = w0;   // pass-through; patched in phase 2
    *reinterpret_cast<float4*>(out + i0 + 4) = w1;
    uint32_t wb[8] = {__float_as_uint(w0.x), __float_as_uint(w0.y),
                      __float_as_uint(w0.z), __float_as_uint(w0.w),
                      __float_as_uint(w1.x), __float_as_uint(w1.y),
                      __float_as_uint(w1.z), __float_as_uint(w1.w)};

    bool fire[8];
    uint32_t ppack[8];
#pragma unroll
    for (int e = 0; e < 8; ++e) {
        uint32_t word = (e < 4) ? xw.x : xw.y;
        uint32_t bx = __byte_perm(word, 0u, 0x4440u | (uint32_t)(e & 3));  // 1 PRMT
        uint4 L  = sL[bx];
        uint2 Lb = sLb[bx];
        uint32_t a, b;
        tf2x32_lut(L.y, L.z, L.w, i0 + (uint32_t)e, P.one, a, b);
        // clamp no-ops (plus@7.0, minus@0.0) pruned via raw bit compare (no F2I)
        fire[e]  = ((a ^ b) < L.x) && (wb[e] != Lb.x);
        ppack[e] = Lb.y;
    }

    // single compaction: shfl inclusive scan of per-thread counts
    uint32_t nf = 0;
#pragma unroll
    for (int e = 0; e < 8; ++e) nf += (uint32_t)fire[e];
    uint32_t incl = nf;
#pragma unroll
    for (int d = 1; d < 32; d <<= 1) {
        uint32_t v = __shfl_up_sync(0xFFFFFFFFu, incl, d);
        if (lane >= (uint32_t)d) incl += v;
    }
    uint32_t wtot = __shfl_sync(0xFFFFFFFFu, incl, 31);
    uint32_t wbase = 0u;
    if (lane == 0 && wtot) wbase = atomicAdd(&s_cnt, wtot);
    wbase = __shfl_sync(0xFFFFFFFFu, wbase, 0);

    uint32_t pos = wbase + (incl - nf);
    uint32_t listbase = blk * SLOTS;
#pragma unroll
    for (int e = 0; e < 8; ++e) {
        if (fire[e]) {
            if (pos < SLOTS)
                g_list[listbase + pos] = (i0 + (uint32_t)e) | ppack[e];
            pos++;
        }
    }

    __syncthreads();
    if (tid == 0) g_cnt[blk] = min(s_cnt, (uint32_t)SLOTS);
}

// Phase 2: F + umin draws for survivors only; scatter +-1 updates.
// wi re-read from out[idx] (phase 1 copy is complete before this launch).
__global__ void __launch_bounds__(256) stdp_fire(float* __restrict__ out, Params P) {
    __shared__ uint32_t sTF9[16];
    __shared__ uint32_t s_n;
    if (threadIdx.x < 16) sTF9[threadIdx.x] = P.TF9[threadIdx.x];
    if (threadIdx.x == 0) s_n = g_cnt[blockIdx.x];
    __syncthreads();

    uint32_t t = threadIdx.x;
    if (t >= s_n) return;

    uint32_t entry = g_list[blockIdx.x * SLOTS + t];
    uint32_t idx  = entry & 0x00FFFFFFu;
    bool     plus = (entry >> 27) & 1u;

    int wi = (int)out[idx];                        // exact int 0..7

    int ks = plus ? 3 : 2;
    uint32_t a, b;
    tf2x32_lut(P.k0[ks], P.k1[ks], P.ks2[ks], idx, P.one, a, b);
    uint32_t abf = a ^ b;
    tf2x32_lut(P.k0[4], P.k1[4], P.ks2[4], idx, P.one, a, b);
    uint32_t abu = a ^ b;

    uint32_t TF9 = sTF9[(plus ? 8 : 0) + wi];
    bool doit = (abf < TF9) || (abu < P.Tumin9);
    if (doit) {
        int nw = wi + (plus ? 1 : -1);
        nw = min(max(nw, 0), 7);                   // unreachable clamp kept for safety
        out[idx] = (float)nw;
    }
}

static inline uint32_t thresh_from_prob(float p) {
    if (p <= 0.0f) return 0u;
    double v = ceil((double)p * 8388608.0);        // 2^23; u=m*2^-23 exactly
    if (v < 0.0) return 0u;
    if (v > 4294967295.0) return 0xFFFFFFFFu;
    return (uint32_t)v;
}

static inline uint32_t shl9_clamp(uint32_t T) {
    uint64_t v = (uint64_t)T << 9;                 // m<T <=> (o0^o1) < (T<<9)
    return v > 0xFFFFFFFFull ? 0xFFFFFFFFu : (uint32_t)v;
}

extern "C" void kernel_launch(void* const* d_in, const int* in_sizes, int n_in,
                              void* d_out, int out_size) {
    const float* w    = (const float*)d_in[0];
    const int*   inS  = (const int*)d_in[1];
    const int*   outS = (const int*)d_in[2];

    Params P;
    for (int j = 0; j < 5; ++j) {
        tf2x32_host(0u, 42u, 0u, (uint32_t)j, P.k0[j], P.k1[j]);
        P.ks2[j] = P.k0[j] ^ P.k1[j] ^ 0x1BD11BDAu;
    }

    P.Tcap9    = shl9_clamp(thresh_from_prob((float)0.102));
    P.Tminus9  = shl9_clamp(thresh_from_prob((float)0.051));
    P.Tsearch9 = shl9_clamp(thresh_from_prob((float)0.032));
    P.Tback9   = shl9_clamp(thresh_from_prob((float)0.96));
    P.Tumin9   = shl9_clamp(thresh_from_prob((float)0.008));

    const float inv7 = (float)(1.0 / 7.0);
    for (int ww = 0; ww < 8; ++ww) {
        float rr = (float)ww * inv7;
        float a  = (1.0f - rr) * (1.0f + rr);      // F_minus prob
        float b  = rr * (2.0f - rr);               // F_plus prob
        P.TF9[ww]     = shl9_clamp(thresh_from_prob(a));
        P.TF9[8 + ww] = shl9_clamp(thresh_from_prob(b));
    }
    P.one = 1u;

    prep_kernel<<<(YTAB_N + XTAB_N + 255) / 256, 256>>>(inS, outS);
    stdp_gate<<<NBLK, 128>>>(w, (float*)d_out, P);
    stdp_fire<<<NBLK, 256>>>((float*)d_out, P);
}

// round 9
// speedup vs baseline: 2.9486x; 1.0965x over previous
#include <cuda_runtime.h>
#include <cstdint>
#include <math.h>

// ModSTDP: bit-exact replay of JAX threefry2x32 (partitionable scheme) STDP update.
// weight shape (R,C,COUT,CIN,KH,KW) = (16,16,64,16,8,8) -> 16,777,216 f32 elements.
// STRIDE=0 => bx depends only on (ci,kh,kw) [1024 vals]; by on (o,r,c): one value
// per 1024-element block.
//
// R9: R8 fused design with the misalignment fixed — s_patch gets __align__(16)
// so the uint4 accesses are legal. Single fused kernel: gate draw for all
// elements; survivors compacted into a smem list (<=256/block, mean ~112);
// survivor stage (2 more draws) patches float bits in smem; owners select and
// write `out` exactly once, coalesced.

#define N_ELEMS   16777216
#define XTAB_N    1024     // CIN*KH*KW
#define NBLK      16384    // blocks (1024 elements each)
#define SLOTS     256      // smem survivor slots per block

__device__ uint8_t g_xtab[XTAB_N];

struct Params {
    uint32_t k0[5], k1[5], ks2[5];                // subkeys + precomputed ks2
    uint32_t Tsearch9, Tcap9, Tback9, Tminus9, Tumin9;  // thresholds << 9
    uint32_t TF9[16];                             // [0..7]=F_minus<<9, [8..15]=F_plus<<9
    uint32_t one;                                 // runtime 1 (opaque to ptxas) for mad.lo
};

// add on the IMAD (fma) pipe: a*one + b with one==1 at runtime
__device__ __forceinline__ uint32_t addI(uint32_t a, uint32_t one, uint32_t b) {
    uint32_t r;
    asm("mad.lo.u32 %0, %1, %2, %3;" : "=r"(r) : "r"(a), "r"(one), "r"(b));
    return r;
}

// Threefry-2x32, 20 rounds. ks2 precomputed; all adds on IMAD pipe.
// alu pipe sees only 20 SHF + 20 LOP3.
__device__ __forceinline__ void tf2x32_lut(uint32_t k0, uint32_t k1, uint32_t ks2,
                                           uint32_t idx, uint32_t one,
                                           uint32_t& o0, uint32_t& o1) {
    uint32_t ks2p1 = addI(ks2, one, 1u);
    uint32_t k0p2  = addI(k0,  one, 2u);
    uint32_t k1p3  = addI(k1,  one, 3u);
    uint32_t ks2p4 = addI(ks2, one, 4u);
    uint32_t k0p5  = addI(k0,  one, 5u);
    uint32_t x0 = k0;                 // 0 + k0
    uint32_t x1 = addI(idx, one, k1);
#define TFR(r) { x0 = addI(x0, one, x1); x1 = __funnelshift_l(x1, x1, r); x1 ^= x0; }
    TFR(13) TFR(15) TFR(26) TFR(6)   x0 = addI(x0, one, k1);  x1 = addI(x1, one, ks2p1);
    TFR(17) TFR(29) TFR(16) TFR(24)  x0 = addI(x0, one, ks2); x1 = addI(x1, one, k0p2);
    TFR(13) TFR(15) TFR(26) TFR(6)   x0 = addI(x0, one, k0);  x1 = addI(x1, one, k1p3);
    TFR(17) TFR(29) TFR(16) TFR(24)  x0 = addI(x0, one, k1);  x1 = addI(x1, one, ks2p4);
    TFR(13) TFR(15) TFR(26) TFR(6)   x0 = addI(x0, one, ks2); x1 = addI(x1, one, k0p5);
#undef TFR
    o0 = x0; o1 = x1;
}

// Host variant for subkey derivation
static inline void tf2x32_host(uint32_t k0, uint32_t k1,
                               uint32_t x0, uint32_t x1,
                               uint32_t& o0, uint32_t& o1) {
    auto rot = [](uint32_t x, int r) { return (x << r) | (x >> (32 - r)); };
    uint32_t ks2 = k0 ^ k1 ^ 0x1BD11BDAu;
    x0 += k0; x1 += k1;
#define TFRH(r) { x0 += x1; x1 = rot(x1, r); x1 ^= x0; }
    TFRH(13) TFRH(15) TFRH(26) TFRH(6)   x0 += k1;  x1 += ks2 + 1u;
    TFRH(17) TFRH(29) TFRH(16) TFRH(24)  x0 += ks2; x1 += k0  + 2u;
    TFRH(13) TFRH(15) TFRH(26) TFRH(6)   x0 += k0;  x1 += k1  + 3u;
    TFRH(17) TFRH(29) TFRH(16) TFRH(24)  x0 += k1;  x1 += ks2 + 4u;
    TFRH(13) TFRH(15) TFRH(26) TFRH(6)   x0 += ks2; x1 += k0  + 5u;
#undef TFRH
    o0 = x0; o1 = x1;
}

// prep: xtab only (x_times = 7 - sum_t input_spikes), 1024 entries
__global__ void __launch_bounds__(256) prep_kernel(const int* __restrict__ inS) {
    int u = blockIdx.x * 256 + threadIdx.x;
    if (u < XTAB_N) {
        int s = 0;
#pragma unroll
        for (int tt = 0; tt < 7; ++tt) s += inS[tt * XTAB_N + u];
        g_xtab[u] = (uint8_t)(7 - s);
    }
}

// Fused kernel: 128 threads x 8 elements = 1024 elements = one (r,c,o) group.
__global__ void __launch_bounds__(128) stdp_fused(const float* __restrict__ w,
                                                  const int* __restrict__ outS,
                                                  float* __restrict__ out,
                                                  Params P) {
    __shared__ uint4    sL[8];                        // per-bx: {Tg9|plus, kg0, kg1, ks2}
    __shared__ uint32_t sTF9[16];
    __shared__ uint32_t s_list[SLOTS];                // survivor entries: le | plus<<10
    __shared__ uint32_t s_cnt;
    __shared__ __align__(16) uint32_t s_patch[1024];  // patched float bits; 0xFFFFFFFF = none

    uint32_t tid = threadIdx.x, lane = tid & 31u, blk = blockIdx.x;
    if (tid == 0) s_cnt = 0u;
    if (tid < 16) sTF9[tid] = P.TF9[tid];
    if (tid < 8) {
        // by for this block: y_times = 7 - sum_t outS[t][o*256+r*16+c]
        uint32_t o = blk & 63u, c = (blk >> 6) & 15u, r = (blk >> 10) & 15u;
        uint32_t ypos = o * 256u + r * 16u + c;
        int s = 0;
#pragma unroll
        for (int tt = 0; tt < 7; ++tt) s += outS[tt * 16384 + ypos];
        uint32_t by = (uint32_t)(7 - s);
        bool B = (by == 7u);
        uint32_t bx = tid;
        bool A = (bx == 7u);
        bool plus = !A && (B || bx <= by);
        uint32_t Tg9 = plus ? (B ? P.Tsearch9 : P.Tcap9)
                            : (A ? (B ? 0u : P.Tback9) : P.Tminus9);
        int ks = plus ? 0 : 1;
        // Tg9 = T<<9 -> bit 0 free for the plus flag (unmasked exactly below)
        sL[bx] = make_uint4(Tg9 | (plus ? 1u : 0u), P.k0[ks], P.k1[ks], P.ks2[ks]);
    }
    // init patch sentinel: 1024 words / 128 threads = 8 words each
    {
        uint4 ff = make_uint4(0xFFFFFFFFu, 0xFFFFFFFFu, 0xFFFFFFFFu, 0xFFFFFFFFu);
        *reinterpret_cast<uint4*>(&s_patch[tid * 8u])     = ff;
        *reinterpret_cast<uint4*>(&s_patch[tid * 8u + 4]) = ff;
    }
    __syncthreads();

    uint32_t i0 = blk * 1024u + tid * 8u;
    uint32_t khkw = i0 & 63u, ci = (i0 >> 6) & 15u;
    uint2 xw = *reinterpret_cast<const uint2*>(&g_xtab[ci * 64u + khkw]); // 8 bx bytes

    float4 w0 = *reinterpret_cast<const float4*>(w + i0);
    float4 w1 = *reinterpret_cast<const float4*>(w + i0 + 4);

    // ---- gate: 8 independent threefry chains ----
    bool fire[8];
    uint32_t pflag[8];
#pragma unroll
    for (int e = 0; e < 8; ++e) {
        uint32_t word = (e < 4) ? xw.x : xw.y;
        uint32_t bx = __byte_perm(word, 0u, 0x4440u | (uint32_t)(e & 3));
        uint4 L = sL[bx];
        uint32_t a, b;
        tf2x32_lut(L.y, L.z, L.w, i0 + (uint32_t)e, P.one, a, b);
        fire[e]  = (a ^ b) < (L.x & ~1u);
        pflag[e] = L.x & 1u;
    }

    // ---- compaction: shfl inclusive scan ----
    uint32_t nf = 0;
#pragma unroll
    for (int e = 0; e < 8; ++e) nf += (uint32_t)fire[e];
    uint32_t incl = nf;
#pragma unroll
    for (int d = 1; d < 32; d <<= 1) {
        uint32_t v = __shfl_up_sync(0xFFFFFFFFu, incl, d);
        if (lane >= (uint32_t)d) incl += v;
    }
    uint32_t wtot = __shfl_sync(0xFFFFFFFFu, incl, 31);
    uint32_t wbase = 0u;
    if (lane == 0 && wtot) wbase = atomicAdd(&s_cnt, wtot);
    wbase = __shfl_sync(0xFFFFFFFFu, wbase, 0);

    uint32_t pos = wbase + (incl - nf);
    uint32_t le0 = tid * 8u;
#pragma unroll
    for (int e = 0; e < 8; ++e) {
        if (fire[e]) {
            if (pos < SLOTS)
                s_list[pos] = (le0 + (uint32_t)e) | (pflag[e] << 10);
            pos++;
        }
    }
    __syncthreads();

    // ---- survivor stage: 2 draws each, patch float bits in smem ----
    uint32_t n = min(s_cnt, (uint32_t)SLOTS);
    for (uint32_t t = tid; t < n; t += 128u) {
        uint32_t entry = s_list[t];
        uint32_t le   = entry & 1023u;
        bool     plus = (entry >> 10) & 1u;
        uint32_t gidx = blk * 1024u + le;

        int wi = (int)w[gidx];                      // L1-hot (just read by this block)
        bool noop = plus ? (wi == 7) : (wi == 0);   // clamp-identity
        if (!noop) {
            int ks = plus ? 3 : 2;
            uint32_t a, b;
            tf2x32_lut(P.k0[ks], P.k1[ks], P.ks2[ks], gidx, P.one, a, b);
            uint32_t abf = a ^ b;
            tf2x32_lut(P.k0[4], P.k1[4], P.ks2[4], gidx, P.one, a, b);
            uint32_t abu = a ^ b;
            uint32_t TF9 = sTF9[(plus ? 8 : 0) + wi];
            if ((abf < TF9) || (abu < P.Tumin9)) {
                int nw = wi + (plus ? 1 : -1);      // stays in [0,7] (noop pruned)
                s_patch[le] = __float_as_uint((float)nw);
            }
        }
    }
    __syncthreads();

    // ---- final: select patch vs original, single coalesced write ----
    uint32_t pb[8];
    *reinterpret_cast<uint4*>(pb)     = *reinterpret_cast<const uint4*>(&s_patch[le0]);
    *reinterpret_cast<uint4*>(pb + 4) = *reinterpret_cast<const uint4*>(&s_patch[le0 + 4]);
    uint32_t wb[8] = {__float_as_uint(w0.x), __float_as_uint(w0.y),
                      __float_as_uint(w0.z), __float_as_uint(w0.w),
                      __float_as_uint(w1.x), __float_as_uint(w1.y),
                      __float_as_uint(w1.z), __float_as_uint(w1.w)};
#pragma unroll
    for (int e = 0; e < 8; ++e)
        if (pb[e] != 0xFFFFFFFFu) wb[e] = pb[e];
    *reinterpret_cast<uint4*>(out + i0)     = make_uint4(wb[0], wb[1], wb[2], wb[3]);
    *reinterpret_cast<uint4*>(out + i0 + 4) = make_uint4(wb[4], wb[5], wb[6], wb[7]);
}

static inline uint32_t thresh_from_prob(float p) {
    if (p <= 0.0f) return 0u;
    double v = ceil((double)p * 8388608.0);       // 2^23; u=m*2^-23 exactly
    if (v < 0.0) return 0u;
    if (v > 4294967295.0) return 0xFFFFFFFFu;
    return (uint32_t)v;
}

static inline uint32_t shl9_clamp(uint32_t T) {
    uint64_t v = (uint64_t)T << 9;                // m<T <=> (o0^o1) < (T<<9)
    return v > 0xFFFFFFFFull ? 0xFFFFFFFFu : (uint32_t)v;
}

extern "C" void kernel_launch(void* const* d_in, const int* in_sizes, int n_in,
                              void* d_out, int out_size) {
    const float* w    = (const float*)d_in[0];
    const int*   inS  = (const int*)d_in[1];
    const int*   outS = (const int*)d_in[2];

    Params P;
    for (int j = 0; j < 5; ++j) {
        tf2x32_host(0u, 42u, 0u, (uint32_t)j, P.k0[j], P.k1[j]);
        P.ks2[j] = P.k0[j] ^ P.k1[j] ^ 0x1BD11BDAu;
    }

    P.Tcap9    = shl9_clamp(thresh_from_prob((float)0.102));
    P.Tminus9  = shl9_clamp(thresh_from_prob((float)0.051));
    P.Tsearch9 = shl9_clamp(thresh_from_prob((float)0.032));
    P.Tback9   = shl9_clamp(thresh_from_prob((float)0.96));
    P.Tumin9   = shl9_clamp(thresh_from_prob((float)0.008));

    const float inv7 = (float)(1.0 / 7.0);
    for (int ww = 0; ww < 8; ++ww) {
        float rr = (float)ww * inv7;
        float a  = (1.0f - rr) * (1.0f + rr);     // F_minus prob
        float b  = rr * (2.0f - rr);              // F_plus prob
        P.TF9[ww]     = shl9_clamp(thresh_from_prob(a));
        P.TF9[8 + ww] = shl9_clamp(thresh_from_prob(b));
    }
    P.one = 1u;

    prep_kernel<<<(XTAB_N + 255) / 256, 256>>>(inS);
    stdp_fused<<<NBLK, 128>>>(w, outS, (float*)d_out, P);
}

// round 10
// speedup vs baseline: 2.9555x; 1.0023x over previous
#include <cuda_runtime.h>
#include <cstdint>
#include <math.h>

// ModSTDP: bit-exact replay of JAX threefry2x32 (partitionable scheme) STDP update.
// weight shape (R,C,COUT,CIN,KH,KW) = (16,16,64,16,8,8) -> 16,777,216 f32 elements.
// STRIDE=0 => bx depends only on (ci,kh,kw) [1024 vals]; by on (o,r,c): one value
// per 1024-element block.
//
// R10: slim the fused kernel. Pass-through `out = w` written early (coalesced);
// survivors scatter 4B STGs to out after the block barrier (no smem patch
// buffer, no select pass). Gate results packed into a single fireMask register
// (plus-flag re-derived in the rare list-write path). Fire compare fused to a
// single LOP3: for even T, v<T <=> (v|1) < (T|plusflag).

#define N_ELEMS   16777216
#define XTAB_N    1024     // CIN*KH*KW
#define NBLK      16384    // blocks (1024 elements each)
#define SLOTS     256      // smem survivor slots per block

__device__ uint8_t g_xtab[XTAB_N];

struct Params {
    uint32_t k0[5], k1[5], ks2[5];                // subkeys + precomputed ks2
    uint32_t Tsearch9, Tcap9, Tback9, Tminus9, Tumin9;  // thresholds << 9
    uint32_t TF9[16];                             // [0..7]=F_minus<<9, [8..15]=F_plus<<9
    uint32_t one;                                 // runtime 1 (opaque to ptxas) for mad.lo
};

// add on the IMAD (fma) pipe: a*one + b with one==1 at runtime
__device__ __forceinline__ uint32_t addI(uint32_t a, uint32_t one, uint32_t b) {
    uint32_t r;
    asm("mad.lo.u32 %0, %1, %2, %3;" : "=r"(r) : "r"(a), "r"(one), "r"(b));
    return r;
}

// Threefry-2x32, 20 rounds. ks2 precomputed; all adds on IMAD pipe.
// alu pipe sees only 20 SHF + 20 LOP3.
__device__ __forceinline__ void tf2x32_lut(uint32_t k0, uint32_t k1, uint32_t ks2,
                                           uint32_t idx, uint32_t one,
                                           uint32_t& o0, uint32_t& o1) {
    uint32_t ks2p1 = addI(ks2, one, 1u);
    uint32_t k0p2  = addI(k0,  one, 2u);
    uint32_t k1p3  = addI(k1,  one, 3u);
    uint32_t ks2p4 = addI(ks2, one, 4u);
    uint32_t k0p5  = addI(k0,  one, 5u);
    uint32_t x0 = k0;                 // 0 + k0
    uint32_t x1 = addI(idx, one, k1);
#define TFR(r) { x0 = addI(x0, one, x1); x1 = __funnelshift_l(x1, x1, r); x1 ^= x0; }
    TFR(13) TFR(15) TFR(26) TFR(6)   x0 = addI(x0, one, k1);  x1 = addI(x1, one, ks2p1);
    TFR(17) TFR(29) TFR(16) TFR(24)  x0 = addI(x0, one, ks2); x1 = addI(x1, one, k0p2);
    TFR(13) TFR(15) TFR(26) TFR(6)   x0 = addI(x0, one, k0);  x1 = addI(x1, one, k1p3);
    TFR(17) TFR(29) TFR(16) TFR(24)  x0 = addI(x0, one, k1);  x1 = addI(x1, one, ks2p4);
    TFR(13) TFR(15) TFR(26) TFR(6)   x0 = addI(x0, one, ks2); x1 = addI(x1, one, k0p5);
#undef TFR
    o0 = x0; o1 = x1;
}

// Host variant for subkey derivation
static inline void tf2x32_host(uint32_t k0, uint32_t k1,
                               uint32_t x0, uint32_t x1,
                               uint32_t& o0, uint32_t& o1) {
    auto rot = [](uint32_t x, int r) { return (x << r) | (x >> (32 - r)); };
    uint32_t ks2 = k0 ^ k1 ^ 0x1BD11BDAu;
    x0 += k0; x1 += k1;
#define TFRH(r) { x0 += x1; x1 = rot(x1, r); x1 ^= x0; }
    TFRH(13) TFRH(15) TFRH(26) TFRH(6)   x0 += k1;  x1 += ks2 + 1u;
    TFRH(17) TFRH(29) TFRH(16) TFRH(24)  x0 += ks2; x1 += k0  + 2u;
    TFRH(13) TFRH(15) TFRH(26) TFRH(6)   x0 += k0;  x1 += k1  + 3u;
    TFRH(17) TFRH(29) TFRH(16) TFRH(24)  x0 += k1;  x1 += ks2 + 4u;
    TFRH(13) TFRH(15) TFRH(26) TFRH(6)   x0 += ks2; x1 += k0  + 5u;
#undef TFRH
    o0 = x0; o1 = x1;
}

// prep: xtab only (x_times = 7 - sum_t input_spikes), 1024 entries
__global__ void __launch_bounds__(256) prep_kernel(const int* __restrict__ inS) {
    int u = blockIdx.x * 256 + threadIdx.x;
    if (u < XTAB_N) {
        int s = 0;
#pragma unroll
        for (int tt = 0; tt < 7; ++tt) s += inS[tt * XTAB_N + u];
        g_xtab[u] = (uint8_t)(7 - s);
    }
}

// Fused kernel: 128 threads x 8 elements = 1024 elements = one (r,c,o) group.
__global__ void __launch_bounds__(128) stdp_fused(const float* __restrict__ w,
                                                  const int* __restrict__ outS,
                                                  float* __restrict__ out,
                                                  Params P) {
    __shared__ uint4    sL[8];          // per-bx: {Tg9|plus, kg0, kg1, ks2}
    __shared__ uint32_t sTF9[16];
    __shared__ uint32_t s_list[SLOTS];  // survivor entries: le | plus<<10
    __shared__ uint32_t s_cnt;

    uint32_t tid = threadIdx.x, lane = tid & 31u, blk = blockIdx.x;
    if (tid == 0) s_cnt = 0u;
    if (tid < 16) sTF9[tid] = P.TF9[tid];
    if (tid < 8) {
        // by for this block: y_times = 7 - sum_t outS[t][o*256+r*16+c]
        uint32_t o = blk & 63u, c = (blk >> 6) & 15u, r = (blk >> 10) & 15u;
        uint32_t ypos = o * 256u + r * 16u + c;
        int s = 0;
#pragma unroll
        for (int tt = 0; tt < 7; ++tt) s += outS[tt * 16384 + ypos];
        uint32_t by = (uint32_t)(7 - s);
        bool B = (by == 7u);
        uint32_t bx = tid;
        bool A = (bx == 7u);
        bool plus = !A && (B || bx <= by);
        uint32_t Tg9 = plus ? (B ? P.Tsearch9 : P.Tcap9)
                            : (A ? (B ? 0u : P.Tback9) : P.Tminus9);
        int ks = plus ? 0 : 1;
        // Tg9 is a multiple of 512 -> bit 0 carries the plus flag; the gate
        // compare uses (v|1) < (Tg9|plus), exact for even Tg9.
        sL[bx] = make_uint4(Tg9 | (plus ? 1u : 0u), P.k0[ks], P.k1[ks], P.ks2[ks]);
    }
    __syncthreads();

    uint32_t i0 = blk * 1024u + tid * 8u;
    uint32_t khkw = i0 & 63u, ci = (i0 >> 6) & 15u;
    uint2 xw = *reinterpret_cast<const uint2*>(&g_xtab[ci * 64u + khkw]); // 8 bx bytes

    // pass-through copy now; survivors patch out[] with scattered stores after
    // the block barrier below (barrier orders the global accesses in-block).
    {
        float4 w0 = *reinterpret_cast<const float4*>(w + i0);
        float4 w1 = *reinterpret_cast<const float4*>(w + i0 + 4);
        *reinterpret_cast<float4*>(out + i0)     = w0;
        *reinterpret_cast<float4*>(out + i0 + 4) = w1;
    }

    // ---- gate: 8 independent threefry chains, results packed into fireMask ----
    uint32_t fireMask = 0u;
#pragma unroll
    for (int e = 0; e < 8; ++e) {
        uint32_t word = (e < 4) ? xw.x : xw.y;
        uint32_t bx = __byte_perm(word, 0u, 0x4440u | (uint32_t)(e & 3));
        uint4 L = sL[bx];
        uint32_t a, b;
        tf2x32_lut(L.y, L.z, L.w, i0 + (uint32_t)e, P.one, a, b);
        uint32_t m = (a ^ b) | 1u;               // single LOP3
        if (m < L.x) fireMask |= (1u << e);
    }

    // ---- compaction: shfl inclusive scan of per-thread counts ----
    uint32_t nf = (uint32_t)__popc(fireMask);
    uint32_t incl = nf;
#pragma unroll
    for (int d = 1; d < 32; d <<= 1) {
        uint32_t v = __shfl_up_sync(0xFFFFFFFFu, incl, d);
        if (lane >= (uint32_t)d) incl += v;
    }
    uint32_t wtot = __shfl_sync(0xFFFFFFFFu, incl, 31);
    uint32_t wbase = 0u;
    if (lane == 0 && wtot) wbase = atomicAdd(&s_cnt, wtot);
    wbase = __shfl_sync(0xFFFFFFFFu, wbase, 0);

    uint32_t pos = wbase + (incl - nf);
    uint32_t le0 = tid * 8u;
#pragma unroll
    for (int e = 0; e < 8; ++e) {
        if ((fireMask >> e) & 1u) {
            uint32_t word = (e < 4) ? xw.x : xw.y;
            uint32_t bx = __byte_perm(word, 0u, 0x4440u | (uint32_t)(e & 3));
            uint32_t plus = sL[bx].x & 1u;       // re-derive (rare path)
            if (pos < SLOTS)
                s_list[pos] = (le0 + (uint32_t)e) | (plus << 10);
            pos++;
        }
    }
    __syncthreads();   // orders pass-through stores before survivor patch stores

    // ---- survivor stage: 2 draws each, scattered 4B patch stores ----
    uint32_t n = min(s_cnt, (uint32_t)SLOTS);
    for (uint32_t t = tid; t < n; t += 128u) {
        uint32_t entry = s_list[t];
        uint32_t le   = entry & 1023u;
        bool     plus = (entry >> 10) & 1u;
        uint32_t gidx = blk * 1024u + le;

        int wi = (int)w[gidx];                   // L1-hot (block just read it)
        bool noop = plus ? (wi == 7) : (wi == 0);   // clamp-identity
        if (!noop) {
            int ks = plus ? 3 : 2;
            uint32_t a, b;
            tf2x32_lut(P.k0[ks], P.k1[ks], P.ks2[ks], gidx, P.one, a, b);
            uint32_t abf = a ^ b;
            tf2x32_lut(P.k0[4], P.k1[4], P.ks2[4], gidx, P.one, a, b);
            uint32_t abu = a ^ b;
            uint32_t TF9 = sTF9[(plus ? 8 : 0) + wi];
            if ((abf < TF9) || (abu < P.Tumin9)) {
                int nw = wi + (plus ? 1 : -1);   // stays in [0,7] (noop pruned)
                out[gidx] = (float)nw;
            }
        }
    }
}

static inline uint32_t thresh_from_prob(float p) {
    if (p <= 0.0f) return 0u;
    double v = ceil((double)p * 8388608.0);      // 2^23; u=m*2^-23 exactly
    if (v < 0.0) return 0u;
    if (v > 4294967295.0) return 0xFFFFFFFFu;
    return (uint32_t)v;
}

static inline uint32_t shl9_clamp(uint32_t T) {
    uint64_t v = (uint64_t)T << 9;               // m<T <=> (o0^o1) < (T<<9)
    return v > 0xFFFFFFFFull ? 0xFFFFFFFFu : (uint32_t)v;
}

extern "C" void kernel_launch(void* const* d_in, const int* in_sizes, int n_in,
                              void* d_out, int out_size) {
    const float* w    = (const float*)d_in[0];
    const int*   inS  = (const int*)d_in[1];
    const int*   outS = (const int*)d_in[2];

    Params P;
    for (int j = 0; j < 5; ++j) {
        tf2x32_host(0u, 42u, 0u, (uint32_t)j, P.k0[j], P.k1[j]);
        P.ks2[j] = P.k0[j] ^ P.k1[j] ^ 0x1BD11BDAu;
    }

    P.Tcap9    = shl9_clamp(thresh_from_prob((float)0.102));
    P.Tminus9  = shl9_clamp(thresh_from_prob((float)0.051));
    P.Tsearch9 = shl9_clamp(thresh_from_prob((float)0.032));
    P.Tback9   = shl9_clamp(thresh_from_prob((float)0.96));
    P.Tumin9   = shl9_clamp(thresh_from_prob((float)0.008));

    const float inv7 = (float)(1.0 / 7.0);
    for (int ww = 0; ww < 8; ++ww) {
        float rr = (float)ww * inv7;
        float a  = (1.0f - rr) * (1.0f + rr);    // F_minus prob
        float b  = rr * (2.0f - rr);             // F_plus prob
        P.TF9[ww]     = shl9_clamp(thresh_from_prob(a));
        P.TF9[8 + ww] = shl9_clamp(thresh_from_prob(b));
    }
    P.one = 1u;

    prep_kernel<<<(XTAB_N + 255) / 256, 256>>>(inS);
    stdp_fused<<<NBLK, 128>>>(w, outS, (float*)d_out, P);
}

// round 11
// speedup vs baseline: 3.0336x; 1.0264x over previous
#include <cuda_runtime.h>
#include <cstdint>
#include <math.h>

// ModSTDP: bit-exact replay of JAX threefry2x32 (partitionable scheme) STDP update.
// weight shape (R,C,COUT,CIN,KH,KW) = (16,16,64,16,8,8) -> 16,777,216 f32 elements.
// STRIDE=0 => bx depends only on (ci,kh,kw) [1024 vals]; by on (o,r,c): one value
// per 1024-element block.
//
// R11: (a) __launch_bounds__(128,12) -> <=40 regs, 75% occupancy (was 58%);
// (b) hoist the 5 per-call threefry key-injection constants into a second
// per-bx smem LUT (sLc) - replaces 5 IMADs/element with 2 LDS issues.
// Phase-2 keys use constants precomputed on the host in Params.

#define N_ELEMS   16777216
#define XTAB_N    1024     // CIN*KH*KW
#define NBLK      16384    // blocks (1024 elements each)
#define SLOTS     256      // smem survivor slots per block

__device__ uint8_t g_xtab[XTAB_N];

struct Params {
    uint32_t k0[5], k1[5], ks2[5];                // subkeys + precomputed ks2
    uint32_t c1[5], c2[5], c3[5], c4[5], c5[5];   // ks2+1, k0+2, k1+3, ks2+4, k0+5
    uint32_t Tsearch9, Tcap9, Tback9, Tminus9, Tumin9;  // thresholds << 9
    uint32_t TF9[16];                             // [0..7]=F_minus<<9, [8..15]=F_plus<<9
    uint32_t one;                                 // runtime 1 (opaque to ptxas) for mad.lo
};

// add on the IMAD (fma) pipe: a*one + b with one==1 at runtime
__device__ __forceinline__ uint32_t addI(uint32_t a, uint32_t one, uint32_t b) {
    uint32_t r;
    asm("mad.lo.u32 %0, %1, %2, %3;" : "=r"(r) : "r"(a), "r"(one), "r"(b));
    return r;
}

// Threefry-2x32, 20 rounds, with ALL key-schedule constants supplied.
// alu pipe: 20 SHF + 20 LOP3. fma pipe: 21 IMAD (x1 init + 20 round adds) + 10 injections.
__device__ __forceinline__ void tf2x32_pre(uint32_t k0, uint32_t k1, uint32_t ks2,
                                           uint32_t c1, uint32_t c2, uint32_t c3,
                                           uint32_t c4, uint32_t c5,
                                           uint32_t idx, uint32_t one,
                                           uint32_t& o0, uint32_t& o1) {
    uint32_t x0 = k0;                 // 0 + k0
    uint32_t x1 = addI(idx, one, k1);
#define TFR(r) { x0 = addI(x0, one, x1); x1 = __funnelshift_l(x1, x1, r); x1 ^= x0; }
    TFR(13) TFR(15) TFR(26) TFR(6)   x0 = addI(x0, one, k1);  x1 = addI(x1, one, c1);
    TFR(17) TFR(29) TFR(16) TFR(24)  x0 = addI(x0, one, ks2); x1 = addI(x1, one, c2);
    TFR(13) TFR(15) TFR(26) TFR(6)   x0 = addI(x0, one, k0);  x1 = addI(x1, one, c3);
    TFR(17) TFR(29) TFR(16) TFR(24)  x0 = addI(x0, one, k1);  x1 = addI(x1, one, c4);
    TFR(13) TFR(15) TFR(26) TFR(6)   x0 = addI(x0, one, ks2); x1 = addI(x1, one, c5);
#undef TFR
    o0 = x0; o1 = x1;
}

// Host variant for subkey derivation
static inline void tf2x32_host(uint32_t k0, uint32_t k1,
                               uint32_t x0, uint32_t x1,
                               uint32_t& o0, uint32_t& o1) {
    auto rot = [](uint32_t x, int r) { return (x << r) | (x >> (32 - r)); };
    uint32_t ks2 = k0 ^ k1 ^ 0x1BD11BDAu;
    x0 += k0; x1 += k1;
#define TFRH(r) { x0 += x1; x1 = rot(x1, r); x1 ^= x0; }
    TFRH(13) TFRH(15) TFRH(26) TFRH(6)   x0 += k1;  x1 += ks2 + 1u;
    TFRH(17) TFRH(29) TFRH(16) TFRH(24)  x0 += ks2; x1 += k0  + 2u;
    TFRH(13) TFRH(15) TFRH(26) TFRH(6)   x0 += k0;  x1 += k1  + 3u;
    TFRH(17) TFRH(29) TFRH(16) TFRH(24)  x0 += k1;  x1 += ks2 + 4u;
    TFRH(13) TFRH(15) TFRH(26) TFRH(6)   x0 += ks2; x1 += k0  + 5u;
#undef TFRH
    o0 = x0; o1 = x1;
}

// prep: xtab only (x_times = 7 - sum_t input_spikes), 1024 entries
__global__ void __launch_bounds__(256) prep_kernel(const int* __restrict__ inS) {
    int u = blockIdx.x * 256 + threadIdx.x;
    if (u < XTAB_N) {
        int s = 0;
#pragma unroll
        for (int tt = 0; tt < 7; ++tt) s += inS[tt * XTAB_N + u];
        g_xtab[u] = (uint8_t)(7 - s);
    }
}

// Fused kernel: 128 threads x 8 elements = 1024 elements = one (r,c,o) group.
__global__ void __launch_bounds__(128, 12) stdp_fused(const float* __restrict__ w,
                                                      const int* __restrict__ outS,
                                                      float* __restrict__ out,
                                                      Params P) {
    __shared__ uint4    sL[8];          // per-bx: {Tg9|plus, kg0, kg1, ks2}
    __shared__ uint4    sLc[8];         // per-bx: {c1, c2, c3, c4}
    __shared__ uint32_t sLc5[8];        // per-bx: c5
    __shared__ uint32_t sTF9[16];
    __shared__ uint32_t s_list[SLOTS];  // survivor entries: le | plus<<10
    __shared__ uint32_t s_cnt;

    uint32_t tid = threadIdx.x, lane = tid & 31u, blk = blockIdx.x;
    if (tid == 0) s_cnt = 0u;
    if (tid < 16) sTF9[tid] = P.TF9[tid];
    if (tid < 8) {
        // by for this block: y_times = 7 - sum_t outS[t][o*256+r*16+c]
        uint32_t o = blk & 63u, c = (blk >> 6) & 15u, r = (blk >> 10) & 15u;
        uint32_t ypos = o * 256u + r * 16u + c;
        int s = 0;
#pragma unroll
        for (int tt = 0; tt < 7; ++tt) s += outS[tt * 16384 + ypos];
        uint32_t by = (uint32_t)(7 - s);
        bool B = (by == 7u);
        uint32_t bx = tid;
        bool A = (bx == 7u);
        bool plus = !A && (B || bx <= by);
        uint32_t Tg9 = plus ? (B ? P.Tsearch9 : P.Tcap9)
                            : (A ? (B ? 0u : P.Tback9) : P.Tminus9);
        int ks = plus ? 0 : 1;
        // Tg9 is a multiple of 512 -> bit 0 carries the plus flag; the gate
        // compare uses (v|1) < (Tg9|plus), exact for even Tg9.
        sL[bx]   = make_uint4(Tg9 | (plus ? 1u : 0u), P.k0[ks], P.k1[ks], P.ks2[ks]);
        sLc[bx]  = make_uint4(P.c1[ks], P.c2[ks], P.c3[ks], P.c4[ks]);
        sLc5[bx] = P.c5[ks];
    }
    __syncthreads();

    uint32_t i0 = blk * 1024u + tid * 8u;
    uint32_t khkw = i0 & 63u, ci = (i0 >> 6) & 15u;
    uint2 xw = *reinterpret_cast<const uint2*>(&g_xtab[ci * 64u + khkw]); // 8 bx bytes

    // pass-through copy now; survivors patch out[] with scattered stores after
    // the block barrier below (barrier orders the global accesses in-block).
    {
        float4 w0 = *reinterpret_cast<const float4*>(w + i0);
        float4 w1 = *reinterpret_cast<const float4*>(w + i0 + 4);
        *reinterpret_cast<float4*>(out + i0)     = w0;
        *reinterpret_cast<float4*>(out + i0 + 4) = w1;
    }

    // ---- gate: 8 independent threefry chains, results packed into fireMask ----
    uint32_t fireMask = 0u;
#pragma unroll
    for (int e = 0; e < 8; ++e) {
        uint32_t word = (e < 4) ? xw.x : xw.y;
        uint32_t bx = __byte_perm(word, 0u, 0x4440u | (uint32_t)(e & 3));
        uint4 L  = sL[bx];
        uint4 Lc = sLc[bx];
        uint32_t c5 = sLc5[bx];
        uint32_t a, b;
        tf2x32_pre(L.y, L.z, L.w, Lc.x, Lc.y, Lc.z, Lc.w, c5,
                   i0 + (uint32_t)e, P.one, a, b);
        uint32_t m = (a ^ b) | 1u;               // single LOP3
        if (m < L.x) fireMask |= (1u << e);
    }

    // ---- compaction: shfl inclusive scan of per-thread counts ----
    uint32_t nf = (uint32_t)__popc(fireMask);
    uint32_t incl = nf;
#pragma unroll
    for (int d = 1; d < 32; d <<= 1) {
        uint32_t v = __shfl_up_sync(0xFFFFFFFFu, incl, d);
        if (lane >= (uint32_t)d) incl += v;
    }
    uint32_t wtot = __shfl_sync(0xFFFFFFFFu, incl, 31);
    uint32_t wbase = 0u;
    if (lane == 0 && wtot) wbase = atomicAdd(&s_cnt, wtot);
    wbase = __shfl_sync(0xFFFFFFFFu, wbase, 0);

    uint32_t pos = wbase + (incl - nf);
    uint32_t le0 = tid * 8u;
#pragma unroll
    for (int e = 0; e < 8; ++e) {
        if ((fireMask >> e) & 1u) {
            uint32_t word = (e < 4) ? xw.x : xw.y;
            uint32_t bx = __byte_perm(word, 0u, 0x4440u | (uint32_t)(e & 3));
            uint32_t plus = sL[bx].x & 1u;       // re-derive (rare path)
            if (pos < SLOTS)
                s_list[pos] = (le0 + (uint32_t)e) | (plus << 10);
            pos++;
        }
    }
    __syncthreads();   // orders pass-through stores before survivor patch stores

    // ---- survivor stage: 2 draws each, scattered 4B patch stores ----
    uint32_t n = min(s_cnt, (uint32_t)SLOTS);
    for (uint32_t t = tid; t < n; t += 128u) {
        uint32_t entry = s_list[t];
        uint32_t le   = entry & 1023u;
        bool     plus = (entry >> 10) & 1u;
        uint32_t gidx = blk * 1024u + le;

        int wi = (int)w[gidx];                   // L1-hot (block just read it)
        bool noop = plus ? (wi == 7) : (wi == 0);   // clamp-identity
        if (!noop) {
            int ks = plus ? 3 : 2;
            uint32_t a, b;
            tf2x32_pre(P.k0[ks], P.k1[ks], P.ks2[ks],
                       P.c1[ks], P.c2[ks], P.c3[ks], P.c4[ks], P.c5[ks],
                       gidx, P.one, a, b);
            uint32_t abf = a ^ b;
            tf2x32_pre(P.k0[4], P.k1[4], P.ks2[4],
                       P.c1[4], P.c2[4], P.c3[4], P.c4[4], P.c5[4],
                       gidx, P.one, a, b);
            uint32_t abu = a ^ b;
            uint32_t TF9 = sTF9[(plus ? 8 : 0) + wi];
            if ((abf < TF9) || (abu < P.Tumin9)) {
                int nw = wi + (plus ? 1 : -1);   // stays in [0,7] (noop pruned)
                out[gidx] = (float)nw;
            }
        }
    }
}

static inline uint32_t thresh_from_prob(float p) {
    if (p <= 0.0f) return 0u;
    double v = ceil((double)p * 8388608.0);      // 2^23; u=m*2^-23 exactly
    if (v < 0.0) return 0u;
    if (v > 4294967295.0) return 0xFFFFFFFFu;
    return (uint32_t)v;
}

static inline uint32_t shl9_clamp(uint32_t T) {
    uint64_t v = (uint64_t)T << 9;               // m<T <=> (o0^o1) < (T<<9)
    return v > 0xFFFFFFFFull ? 0xFFFFFFFFu : (uint32_t)v;
}

extern "C" void kernel_launch(void* const* d_in, const int* in_sizes, int n_in,
                              void* d_out, int out_size) {
    const float* w    = (const float*)d_in[0];
    const int*   inS  = (const int*)d_in[1];
    const int*   outS = (const int*)d_in[2];

    Params P;
    for (int j = 0; j < 5; ++j) {
        tf2x32_host(0u, 42u, 0u, (uint32_t)j, P.k0[j], P.k1[j]);
        P.ks2[j] = P.k0[j] ^ P.k1[j] ^ 0x1BD11BDAu;
        P.c1[j] = P.ks2[j] + 1u;
        P.c2[j] = P.k0[j]  + 2u;
        P.c3[j] = P.k1[j]  + 3u;
        P.c4[j] = P.ks2[j] + 4u;
        P.c5[j] = P.k0[j]  + 5u;
    }

    P.Tcap9    = shl9_clamp(thresh_from_prob((float)0.102));
    P.Tminus9  = shl9_clamp(thresh_from_prob((float)0.051));
    P.Tsearch9 = shl9_clamp(thresh_from_prob((float)0.032));
    P.Tback9   = shl9_clamp(thresh_from_prob((float)0.96));
    P.Tumin9   = shl9_clamp(thresh_from_prob((float)0.008));

    const float inv7 = (float)(1.0 / 7.0);
    for (int ww = 0; ww < 8; ++ww) {
        float rr = (float)ww * inv7;
        float a  = (1.0f - rr) * (1.0f + rr);    // F_minus prob
        float b  = rr * (2.0f - rr);             // F_plus prob
        P.TF9[ww]     = shl9_clamp(thresh_from_prob(a));
        P.TF9[8 + ww] = shl9_clamp(thresh_from_prob(b));
    }
    P.one = 1u;

    prep_kernel<<<(XTAB_N + 255) / 256, 256>>>(inS);
    stdp_fused<<<NBLK, 128>>>(w, outS, (float*)d_out, P);
}